// round 8
// baseline (speedup 1.0000x reference)
#include <cuda_runtime.h>
#include <cuda_bf16.h>
#include <math.h>
#include <stdint.h>

typedef unsigned short u16;

// Problem constants
#define BB   32
#define NN_  577
#define CC   768
#define HH_  12
#define DD   64
#define HID_ 3072
#define ROWS (BB*NN_)                    // 18464
#define ALPHA_ 0.1f
#define EPS_ 1e-6f
#define SCALE_ 0.125f

// ---------------- scratch --------------------------------------------------
__device__ u16 g_hlnH[(long long)ROWS*CC],  g_hlnL[(long long)ROWS*CC];
__device__ u16 g_qkvwH[(long long)3*CC*CC], g_qkvwL[(long long)3*CC*CC];
__device__ u16 g_projwH[(long long)CC*CC],  g_projwL[(long long)CC*CC];
__device__ u16 g_fc1wH[(long long)HID_*CC], g_fc1wL[(long long)HID_*CC];
__device__ u16 g_fc2wH[(long long)CC*HID_], g_fc2wL[(long long)CC*HID_];
__device__ u16 g_qkvH[(long long)ROWS*3*CC], g_qkvL[(long long)ROWS*3*CC];
__device__ u16 g_aoutH[(long long)ROWS*CC], g_aoutL[(long long)ROWS*CC];
__device__ float g_x1[(long long)ROWS*CC];
__device__ u16 g_h2H[(long long)ROWS*CC],  g_h2L[(long long)ROWS*CC];
__device__ u16 g_fc1H[(long long)ROWS*HID_], g_fc1L[(long long)ROWS*HID_];

// =================== asm helpers ===========================================
#define MMA16816(d, a0,a1,a2,a3, b0,b1) \
    asm volatile("mma.sync.aligned.m16n8k16.row.col.f32.bf16.bf16.f32 " \
        "{%0,%1,%2,%3}, {%4,%5,%6,%7}, {%8,%9}, {%0,%1,%2,%3};" \
        : "+f"((d)[0]), "+f"((d)[1]), "+f"((d)[2]), "+f"((d)[3]) \
        : "r"(a0), "r"(a1), "r"(a2), "r"(a3), "r"(b0), "r"(b1))

#define LDSM4(r, ad) \
    asm volatile("ldmatrix.sync.aligned.m8n8.x4.shared.b16 {%0,%1,%2,%3}, [%4];" \
        : "=r"((r)[0]), "=r"((r)[1]), "=r"((r)[2]), "=r"((r)[3]) : "r"(ad))

#define LDSM4T(r, ad) \
    asm volatile("ldmatrix.sync.aligned.m8n8.x4.trans.shared.b16 {%0,%1,%2,%3}, [%4];" \
        : "=r"((r)[0]), "=r"((r)[1]), "=r"((r)[2]), "=r"((r)[3]) : "r"(ad))

__device__ __forceinline__ void cpa16(uint32_t dst, const void* src, int sz) {
    asm volatile("cp.async.cg.shared.global [%0], [%1], 16, %2;" :: "r"(dst), "l"(src), "r"(sz) : "memory");
}
#define CP_COMMIT() asm volatile("cp.async.commit_group;" ::: "memory")
#define CP_WAIT1()  asm volatile("cp.async.wait_group 1;" ::: "memory")
#define CP_WAIT0()  asm volatile("cp.async.wait_group 0;" ::: "memory")

__device__ __forceinline__ uint32_t smem_u32(const void* p) {
    uint32_t a;
    asm("{ .reg .u64 t; cvta.to.shared.u64 t, %1; cvt.u32.u64 %0, t; }" : "=r"(a) : "l"(p));
    return a;
}
__device__ __forceinline__ uint32_t pack_bf2(float x, float y) {
    __nv_bfloat16 hx = __float2bfloat16_rn(x);
    __nv_bfloat16 hy = __float2bfloat16_rn(y);
    return ((uint32_t)__bfloat16_as_ushort(hy) << 16) | __bfloat16_as_ushort(hx);
}
__device__ __forceinline__ void split_bf(float v, u16& h, u16& l) {
    __nv_bfloat16 hb = __float2bfloat16_rn(v);
    h = __bfloat16_as_ushort(hb);
    l = __bfloat16_as_ushort(__float2bfloat16_rn(v - __bfloat162float(hb)));
}
__device__ __forceinline__ float bf_hi(float v) {
    return __bfloat162float(__float2bfloat16_rn(v));
}

// =================== bf16-pair HMMA GEMM (3-stage, 1 sync/stage) ===========
template<int BN, int EPI, int OUTB>
__global__ void __launch_bounds__(256, 1)
gemm_bf(const u16* __restrict__ AH, const u16* __restrict__ AL,
        const u16* __restrict__ BH, const u16* __restrict__ BL,
        float* __restrict__ C, u16* __restrict__ CH, u16* __restrict__ CL,
        int M, int N, int K, int ldA, int ldB, int ldC,
        const float* __restrict__ bias,
        const float* __restrict__ Res, int ldRes, float alpha)
{
    constexpr int ABYTES = 128 * 80;
    constexpr int BBYTES = BN * 80;
    constexpr int STAGE  = 2*ABYTES + 2*BBYTES;   // 40960 for BN=128
    constexpr int NT     = BN / 16;
    constexpr int BCH    = BN / 64;

    const int tid = threadIdx.x, lane = tid & 31, wid = tid >> 5;
    const int gq = lane >> 2, tq = lane & 3;
    const int warp_m = wid & 3, warp_n = wid >> 2;

    const int rowBase = blockIdx.y * 128;
    const int colBase = blockIdx.x * BN;

    extern __shared__ char smraw[];
    const uint32_t smb = smem_u32(smraw);

    float acc[2][NT][4];
#pragma unroll
    for (int i = 0; i < 2; i++)
#pragma unroll
        for (int j = 0; j < NT; j++)
#pragma unroll
            for (int q = 0; q < 4; q++) acc[i][j][q] = 0.f;

    const int nst = K / 32;

    auto load_stage = [&](int s) {
        const int k0 = s * 32;
        const uint32_t base = smb + (s % 3) * STAGE;
#pragma unroll
        for (int i = 0; i < 2; i++) {
            int cid = tid + i*256;
            int row = cid >> 2, q = cid & 3;
            int gr = rowBase + row;
            int sz = (gr < M) ? 16 : 0;
            long long go = (long long)(gr < M ? gr : 0) * ldA + k0 + q*8;
            uint32_t so = row*80 + q*16;
            cpa16(base + so,          AH + go, sz);
            cpa16(base + ABYTES + so, AL + go, sz);
        }
#pragma unroll
        for (int i = 0; i < BCH; i++) {
            int cid = tid + i*256;
            int row = cid >> 2, q = cid & 3;
            int gn = colBase + row;
            int sz = (gn < N) ? 16 : 0;
            long long go = (long long)(gn < N ? gn : 0) * ldB + k0 + q*8;
            uint32_t so = row*80 + q*16;
            cpa16(base + 2*ABYTES + so,          BH + go, sz);
            cpa16(base + 2*ABYTES + BBYTES + so, BL + go, sz);
        }
    };

    const uint32_t lrow = lane & 15, lsel = lane >> 4;
    const uint32_t aOff = (warp_m*32 + lrow)*80 + lsel*16;
    const uint32_t bOff = (warp_n*(BN/2) + lrow)*80 + lsel*16;

    load_stage(0); CP_COMMIT();
    if (nst > 1) { load_stage(1); CP_COMMIT(); }

    for (int s = 0; s < nst; s++) {
        if (s + 1 < nst) CP_WAIT1(); else CP_WAIT0();
        __syncthreads();

        const uint32_t st = smb + (s % 3) * STAGE;
#pragma unroll
        for (int ks = 0; ks < 2; ks++) {
            uint32_t ah[2][4], al[2][4];
#pragma unroll
            for (int i = 0; i < 2; i++) {
                LDSM4(ah[i], st + aOff + i*1280 + ks*32);
                LDSM4(al[i], st + ABYTES + aOff + i*1280 + ks*32);
            }
#pragma unroll
            for (int j2 = 0; j2 < NT/2; j2++) {
                uint32_t bh[4], bl[4];
                LDSM4(bh, st + 2*ABYTES + bOff + j2*1280 + ks*32);
                LDSM4(bl, st + 2*ABYTES + BBYTES + bOff + j2*1280 + ks*32);
#pragma unroll
                for (int i = 0; i < 2; i++) {
                    MMA16816(acc[i][2*j2],   ah[i][0],ah[i][1],ah[i][2],ah[i][3], bh[0], bh[2]);
                    MMA16816(acc[i][2*j2+1], ah[i][0],ah[i][1],ah[i][2],ah[i][3], bh[1], bh[3]);
                    MMA16816(acc[i][2*j2],   ah[i][0],ah[i][1],ah[i][2],ah[i][3], bl[0], bl[2]);
                    MMA16816(acc[i][2*j2+1], ah[i][0],ah[i][1],ah[i][2],ah[i][3], bl[1], bl[3]);
                    MMA16816(acc[i][2*j2],   al[i][0],al[i][1],al[i][2],al[i][3], bh[0], bh[2]);
                    MMA16816(acc[i][2*j2+1], al[i][0],al[i][1],al[i][2],al[i][3], bh[1], bh[3]);
                }
            }
        }
        if (s + 2 < nst) { load_stage(s + 2); CP_COMMIT(); }
    }

#pragma unroll
    for (int i = 0; i < 2; i++) {
#pragma unroll
        for (int half = 0; half < 2; half++) {
            const int r = rowBase + warp_m*32 + i*16 + gq + half*8;
            if (r >= M) continue;
#pragma unroll
            for (int j = 0; j < NT; j++) {
                const int c0 = colBase + warp_n*(BN/2) + j*8 + tq*2;
                float v0 = acc[i][j][half*2 + 0] * alpha;
                float v1 = acc[i][j][half*2 + 1] * alpha;
                if (bias) { v0 += bias[c0]; v1 += (c0+1 < N) ? bias[c0+1] : 0.f; }
                if (EPI == 1) {
                    v0 = 0.5f*v0*(1.0f + erff(v0*0.70710678118654752f));
                    v1 = 0.5f*v1*(1.0f + erff(v1*0.70710678118654752f));
                } else if (EPI == 2) {
                    v0 += Res[(long long)r*ldRes + c0];
                    if (c0+1 < N) v1 += Res[(long long)r*ldRes + c0 + 1];
                }
                if (OUTB) {
                    if (c0 + 1 < N) {
                        u16 h0,l0,h1,l1;
                        split_bf(v0, h0, l0); split_bf(v1, h1, l1);
                        *reinterpret_cast<uint32_t*>(CH + (long long)r*ldC + c0) = ((uint32_t)h1<<16)|h0;
                        *reinterpret_cast<uint32_t*>(CL + (long long)r*ldC + c0) = ((uint32_t)l1<<16)|l0;
                    } else if (c0 < N) {
                        u16 h0,l0; split_bf(v0, h0, l0);
                        CH[(long long)r*ldC + c0] = h0; CL[(long long)r*ldC + c0] = l0;
                    }
                } else {
                    if (c0 < N)     C[(long long)r*ldC + c0]     = v0;
                    if (c0+1 < N)   C[(long long)r*ldC + c0 + 1] = v1;
                }
            }
        }
    }
}

// =================== fused flash attention =================================
// V loaded key-major directly from qkv; PV B-fragments via ldmatrix.trans.
#define QSTR 144
#define QHALF 18432            // 128*144
#define KBASE (2*QHALF)        // 36864
#define KSTG  (2*QHALF)
#define VBASE (KBASE + 2*KSTG) // 110592
#define VSTG  (2*QHALF)
#define FLASH_SMEM (VBASE + 2*VSTG)   // 184320

__global__ void __launch_bounds__(256, 1)
flash_attn(const u16* __restrict__ qkvH, const u16* __restrict__ qkvL,
           const float* __restrict__ attn_w,
           u16* __restrict__ aoutH, u16* __restrict__ aoutL,
           float* __restrict__ patch_out)
{
    const int z = blockIdx.y, qt = blockIdx.x;
    const int b = z / HH_, h = z % HH_;
    const int tid = threadIdx.x, lane = tid & 31, wid = tid >> 5;
    const int gq = lane >> 2, tq = lane & 3;

    extern __shared__ char smraw[];
    const uint32_t smb = smem_u32(smraw);

    // ---- load Q tile (once) ----
#pragma unroll
    for (int i = 0; i < 4; i++) {
        int cid = tid + i*256;
        int row = cid >> 3, ch = cid & 7;
        int gr = qt*128 + row;
        int sz = (gr < NN_) ? 16 : 0;
        long long go = (long long)(b*NN_ + (gr < NN_ ? gr : 0))*(3*CC) + h*DD + ch*8;
        cpa16(smb + row*QSTR + ch*16,         qkvH + go, sz);
        cpa16(smb + QHALF + row*QSTR + ch*16, qkvL + go, sz);
    }
    auto load_kv = [&](int t) {
        const uint32_t kb = smb + KBASE + (t & 1)*KSTG;
        const uint32_t vb = smb + VBASE + (t & 1)*VSTG;
#pragma unroll
        for (int i = 0; i < 4; i++) {
            int cid = tid + i*256;
            int row = cid >> 3, ch = cid & 7;
            int gk = t*128 + row;
            int sz = (gk < NN_) ? 16 : 0;
            long long base = (long long)(b*NN_ + (gk < NN_ ? gk : 0))*(3*CC) + h*DD + ch*8;
            cpa16(kb + row*QSTR + ch*16,         qkvH + base + CC, sz);
            cpa16(kb + QHALF + row*QSTR + ch*16, qkvL + base + CC, sz);
            cpa16(vb + row*QSTR + ch*16,         qkvH + base + 2*CC, sz);
            cpa16(vb + QHALF + row*QSTR + ch*16, qkvL + base + 2*CC, sz);
        }
    };

    float o[8][4];
#pragma unroll
    for (int j = 0; j < 8; j++)
#pragma unroll
        for (int q = 0; q < 4; q++) o[j][q] = 0.f;
    float m0 = -INFINITY, m1 = -INFINITY, l0 = 0.f, l1 = 0.f;

    const uint32_t lrow = lane & 15, lsel = lane >> 4;
    const uint32_t qOff = (wid*16 + lrow)*QSTR + lsel*16;
    const bool clsrow = (qt == 0) && (wid == 0) && (gq == 0);

    load_kv(0);
    CP_COMMIT();

    for (int t = 0; t < 5; t++) {
        if (t < 4) { load_kv(t + 1); CP_COMMIT(); CP_WAIT1(); }
        else       { CP_WAIT0(); }
        __syncthreads();

        const uint32_t kb = smb + KBASE + (t & 1)*KSTG;
        const uint32_t vb = smb + VBASE + (t & 1)*VSTG;

        // ---- S = Q @ K^T ----
        float s[16][4];
#pragma unroll
        for (int j = 0; j < 16; j++)
#pragma unroll
            for (int q = 0; q < 4; q++) s[j][q] = 0.f;

#pragma unroll
        for (int kg = 0; kg < 4; kg++) {
            uint32_t qh[4], ql[4];
            LDSM4(qh, smb + qOff + kg*32);
            LDSM4(ql, smb + QHALF + qOff + kg*32);
#pragma unroll
            for (int jj = 0; jj < 8; jj++) {
                uint32_t kh[4], kl[4];
                uint32_t ko = kb + (jj*16 + lrow)*QSTR + lsel*16 + kg*32;
                LDSM4(kh, ko);
                LDSM4(kl, ko + QHALF);
                MMA16816(s[2*jj],   qh[0],qh[1],qh[2],qh[3], kh[0], kh[2]);
                MMA16816(s[2*jj+1], qh[0],qh[1],qh[2],qh[3], kh[1], kh[3]);
                MMA16816(s[2*jj],   qh[0],qh[1],qh[2],qh[3], kl[0], kl[2]);
                MMA16816(s[2*jj+1], qh[0],qh[1],qh[2],qh[3], kl[1], kl[3]);
                MMA16816(s[2*jj],   ql[0],ql[1],ql[2],ql[3], kh[0], kh[2]);
                MMA16816(s[2*jj+1], ql[0],ql[1],ql[2],ql[3], kh[1], kh[3]);
            }
        }

        // ---- scale + CLS factor + patch + mask ----
#pragma unroll
        for (int jj = 0; jj < 16; jj++) {
#pragma unroll
            for (int qi = 0; qi < 4; qi++) {
                float v = s[jj][qi] * SCALE_;
                int key = t*128 + jj*8 + tq*2 + (qi & 1);
                if (clsrow && qi < 2) {
                    if (key >= 1 && key < NN_) {
                        patch_out[(long long)z*(NN_-1) + key - 1] = v;
                        v *= attn_w[(long long)b*(NN_-1) + key - 1] * ALPHA_ + (1.0f - ALPHA_);
                    }
                }
                if (key >= NN_) v = -1e30f;
                s[jj][qi] = v;
            }
        }

        // ---- online softmax ----
        float mx0 = -1e30f, mx1 = -1e30f;
#pragma unroll
        for (int jj = 0; jj < 16; jj++) {
            mx0 = fmaxf(mx0, fmaxf(s[jj][0], s[jj][1]));
            mx1 = fmaxf(mx1, fmaxf(s[jj][2], s[jj][3]));
        }
        mx0 = fmaxf(mx0, __shfl_xor_sync(~0u, mx0, 1)); mx0 = fmaxf(mx0, __shfl_xor_sync(~0u, mx0, 2));
        mx1 = fmaxf(mx1, __shfl_xor_sync(~0u, mx1, 1)); mx1 = fmaxf(mx1, __shfl_xor_sync(~0u, mx1, 2));
        float mn0 = fmaxf(m0, mx0), mn1 = fmaxf(m1, mx1);
        float f0 = __expf(m0 - mn0), f1 = __expf(m1 - mn1);
        m0 = mn0; m1 = mn1;
        float rs0 = 0.f, rs1 = 0.f;
#pragma unroll
        for (int jj = 0; jj < 16; jj++) {
            float p0 = __expf(s[jj][0] - m0), p1 = __expf(s[jj][1] - m0);
            float p2 = __expf(s[jj][2] - m1), p3 = __expf(s[jj][3] - m1);
            s[jj][0] = p0; s[jj][1] = p1; s[jj][2] = p2; s[jj][3] = p3;
            rs0 += p0 + p1; rs1 += p2 + p3;
        }
        rs0 += __shfl_xor_sync(~0u, rs0, 1); rs0 += __shfl_xor_sync(~0u, rs0, 2);
        rs1 += __shfl_xor_sync(~0u, rs1, 1); rs1 += __shfl_xor_sync(~0u, rs1, 2);
        l0 = l0*f0 + rs0; l1 = l1*f1 + rs1;
#pragma unroll
        for (int j = 0; j < 8; j++) {
            o[j][0] *= f0; o[j][1] *= f0; o[j][2] *= f1; o[j][3] *= f1;
        }

        // ---- O += P @ V (V key-major, trans ldmatrix) ----
#pragma unroll
        for (int kg = 0; kg < 8; kg++) {
            uint32_t ah[4], al[4];
            {
                float v00 = s[2*kg][0],   v01 = s[2*kg][1],   v02 = s[2*kg][2],   v03 = s[2*kg][3];
                float v10 = s[2*kg+1][0], v11 = s[2*kg+1][1], v12 = s[2*kg+1][2], v13 = s[2*kg+1][3];
                ah[0] = pack_bf2(v00, v01); ah[1] = pack_bf2(v02, v03);
                ah[2] = pack_bf2(v10, v11); ah[3] = pack_bf2(v12, v13);
                al[0] = pack_bf2(v00 - bf_hi(v00), v01 - bf_hi(v01));
                al[1] = pack_bf2(v02 - bf_hi(v02), v03 - bf_hi(v03));
                al[2] = pack_bf2(v10 - bf_hi(v10), v11 - bf_hi(v11));
                al[3] = pack_bf2(v12 - bf_hi(v12), v13 - bf_hi(v13));
            }
#pragma unroll
            for (int jp = 0; jp < 4; jp++) {
                uint32_t vh[4], vl[4];
                uint32_t vo = vb + (kg*16 + lrow)*QSTR + jp*32 + lsel*16;
                LDSM4T(vh, vo);
                LDSM4T(vl, vo + QHALF);
                MMA16816(o[2*jp],   ah[0],ah[1],ah[2],ah[3], vh[0], vh[1]);
                MMA16816(o[2*jp+1], ah[0],ah[1],ah[2],ah[3], vh[2], vh[3]);
                MMA16816(o[2*jp],   ah[0],ah[1],ah[2],ah[3], vl[0], vl[1]);
                MMA16816(o[2*jp+1], ah[0],ah[1],ah[2],ah[3], vl[2], vl[3]);
                MMA16816(o[2*jp],   al[0],al[1],al[2],al[3], vh[0], vh[1]);
                MMA16816(o[2*jp+1], al[0],al[1],al[2],al[3], vh[2], vh[3]);
            }
        }
        __syncthreads();
    }

    // ---- epilogue ----
    const float inv0 = 1.0f / l0, inv1 = 1.0f / l1;
    const int q0 = qt*128 + wid*16 + gq, q1 = q0 + 8;
#pragma unroll
    for (int j = 0; j < 8; j++) {
        int d0 = j*8 + tq*2;
        if (q0 < NN_) {
            float v0 = o[j][0]*inv0, v1 = o[j][1]*inv0;
            u16 h0,lw0,h1,lw1; split_bf(v0,h0,lw0); split_bf(v1,h1,lw1);
            long long off = (long long)(b*NN_ + q0)*CC + h*DD + d0;
            *reinterpret_cast<uint32_t*>(aoutH + off) = ((uint32_t)h1<<16)|h0;
            *reinterpret_cast<uint32_t*>(aoutL + off) = ((uint32_t)lw1<<16)|lw0;
        }
        if (q1 < NN_) {
            float v0 = o[j][2]*inv1, v1 = o[j][3]*inv1;
            u16 h0,lw0,h1,lw1; split_bf(v0,h0,lw0); split_bf(v1,h1,lw1);
            long long off = (long long)(b*NN_ + q1)*CC + h*DD + d0;
            *reinterpret_cast<uint32_t*>(aoutH + off) = ((uint32_t)h1<<16)|h0;
            *reinterpret_cast<uint32_t*>(aoutL + off) = ((uint32_t)lw1<<16)|lw0;
        }
    }
}

// ---------------- weight fp32 -> bf16 hi/lo --------------------------------
__global__ void conv_pair(const float* __restrict__ src, u16* __restrict__ hi,
                          u16* __restrict__ lo, long long n4)
{
    long long i = (long long)blockIdx.x * blockDim.x + threadIdx.x;
    if (i >= n4) return;
    float4 v = reinterpret_cast<const float4*>(src)[i];
    u16 h0,l0,h1,l1,h2,l2,h3,l3;
    split_bf(v.x,h0,l0); split_bf(v.y,h1,l1); split_bf(v.z,h2,l2); split_bf(v.w,h3,l3);
    uint2 hp = { ((uint32_t)h1<<16)|h0, ((uint32_t)h3<<16)|h2 };
    uint2 lp = { ((uint32_t)l1<<16)|l0, ((uint32_t)l3<<16)|l2 };
    reinterpret_cast<uint2*>(hi)[i] = hp;
    reinterpret_cast<uint2*>(lo)[i] = lp;
}

// ---------------- LayerNorm -> bf16 hi/lo ----------------------------------
__global__ void ln_kernel(const float* __restrict__ in,
                          const float* __restrict__ w, const float* __restrict__ b,
                          u16* __restrict__ outH, u16* __restrict__ outL)
{
    const long long row = blockIdx.x;
    const int tid = threadIdx.x;
    const float* rp = in + row * CC;
    float v0 = rp[tid], v1 = rp[tid+256], v2 = rp[tid+512];
    float s = v0+v1+v2, ss = v0*v0 + v1*v1 + v2*v2;
    const int wid = tid >> 5, lid = tid & 31;
    for (int o = 16; o; o >>= 1) { s += __shfl_xor_sync(~0u, s, o); ss += __shfl_xor_sync(~0u, ss, o); }
    __shared__ float rs[8], rq[8];
    if (lid == 0) { rs[wid] = s; rq[wid] = ss; }
    __syncthreads();
    float ts = 0.f, tq = 0.f;
#pragma unroll
    for (int i = 0; i < 8; i++) { ts += rs[i]; tq += rq[i]; }
    float mean = ts * (1.0f/CC);
    float rstd = rsqrtf(tq * (1.0f/CC) - mean*mean + EPS_);
#pragma unroll
    for (int k = 0; k < 3; k++) {
        int c = tid + k*256;
        float v = (k==0?v0:(k==1?v1:v2));
        float y = (v - mean)*rstd * w[c] + b[c];
        u16 h,l; split_bf(y,h,l);
        outH[row*CC + c] = h; outL[row*CC + c] = l;
    }
}

// ---------------------------------------------------------------------------
extern "C" void kernel_launch(void* const* d_in, const int* in_sizes, int n_in,
                              void* d_out, int out_size)
{
    const float* x      = (const float*)d_in[0];
    const float* attn_w = (const float*)d_in[1];
    const float* ln1_w  = (const float*)d_in[2];
    const float* ln1_b  = (const float*)d_in[3];
    const float* qkv_w  = (const float*)d_in[4];
    const float* qkv_b  = (const float*)d_in[5];
    const float* proj_w = (const float*)d_in[6];
    const float* proj_b = (const float*)d_in[7];
    const float* ln2_w  = (const float*)d_in[8];
    const float* ln2_b  = (const float*)d_in[9];
    const float* fc1_w  = (const float*)d_in[10];
    const float* fc1_b  = (const float*)d_in[11];
    const float* fc2_w  = (const float*)d_in[12];
    const float* fc2_b  = (const float*)d_in[13];

    float* out_x     = (float*)d_out;
    float* out_patch = out_x + (long long)ROWS*CC;

    u16 *hlnH,*hlnL,*qkvwH,*qkvwL,*projwH,*projwL,*fc1wH,*fc1wL,*fc2wH,*fc2wL;
    u16 *qkvH,*qkvL,*aoutH,*aoutL,*h2H,*h2L,*fc1H,*fc1L;
    float *x1;
    cudaGetSymbolAddress((void**)&hlnH, g_hlnH);   cudaGetSymbolAddress((void**)&hlnL, g_hlnL);
    cudaGetSymbolAddress((void**)&qkvwH, g_qkvwH); cudaGetSymbolAddress((void**)&qkvwL, g_qkvwL);
    cudaGetSymbolAddress((void**)&projwH, g_projwH); cudaGetSymbolAddress((void**)&projwL, g_projwL);
    cudaGetSymbolAddress((void**)&fc1wH, g_fc1wH); cudaGetSymbolAddress((void**)&fc1wL, g_fc1wL);
    cudaGetSymbolAddress((void**)&fc2wH, g_fc2wH); cudaGetSymbolAddress((void**)&fc2wL, g_fc2wL);
    cudaGetSymbolAddress((void**)&qkvH, g_qkvH);   cudaGetSymbolAddress((void**)&qkvL, g_qkvL);
    cudaGetSymbolAddress((void**)&aoutH, g_aoutH); cudaGetSymbolAddress((void**)&aoutL, g_aoutL);
    cudaGetSymbolAddress((void**)&x1, g_x1);
    cudaGetSymbolAddress((void**)&h2H, g_h2H);     cudaGetSymbolAddress((void**)&h2L, g_h2L);
    cudaGetSymbolAddress((void**)&fc1H, g_fc1H);   cudaGetSymbolAddress((void**)&fc1L, g_fc1L);

    const int SMEM128 = 3 * (2*128*80 + 2*128*80);   // 122880
    cudaFuncSetAttribute(gemm_bf<128,0,1>, cudaFuncAttributeMaxDynamicSharedMemorySize, SMEM128);
    cudaFuncSetAttribute(gemm_bf<128,1,1>, cudaFuncAttributeMaxDynamicSharedMemorySize, SMEM128);
    cudaFuncSetAttribute(gemm_bf<128,2,0>, cudaFuncAttributeMaxDynamicSharedMemorySize, SMEM128);
    cudaFuncSetAttribute(flash_attn, cudaFuncAttributeMaxDynamicSharedMemorySize, FLASH_SMEM);

    // 0) weight conversions
    conv_pair<<<(int)(((long long)3*CC*CC/4 + 255)/256), 256>>>(qkv_w,  qkvwH,  qkvwL,  (long long)3*CC*CC/4);
    conv_pair<<<(int)(((long long)CC*CC/4   + 255)/256), 256>>>(proj_w, projwH, projwL, (long long)CC*CC/4);
    conv_pair<<<(int)(((long long)HID_*CC/4 + 255)/256), 256>>>(fc1_w,  fc1wH,  fc1wL,  (long long)HID_*CC/4);
    conv_pair<<<(int)(((long long)CC*HID_/4 + 255)/256), 256>>>(fc2_w,  fc2wH,  fc2wL,  (long long)CC*HID_/4);

    // 1) LN1 -> bf16 pair
    ln_kernel<<<ROWS, 256>>>(x, ln1_w, ln1_b, hlnH, hlnL);

    // 2) qkv GEMM -> bf16 pair
    gemm_bf<128,0,1><<<dim3(3*CC/128, (ROWS+127)/128, 1), 256, SMEM128>>>(
        hlnH, hlnL, qkvwH, qkvwL, nullptr, qkvH, qkvL,
        ROWS, 3*CC, CC, CC, CC, 3*CC, qkv_b, nullptr, 0, 1.0f);

    // 3) fused flash attention
    flash_attn<<<dim3(5, BB*HH_), 256, FLASH_SMEM>>>(
        qkvH, qkvL, attn_w, aoutH, aoutL, out_patch);

    // 4) x1 = x + aout @ proj_w^T + proj_b
    gemm_bf<128,2,0><<<dim3(CC/128, (ROWS+127)/128, 1), 256, SMEM128>>>(
        aoutH, aoutL, projwH, projwL, x1, nullptr, nullptr,
        ROWS, CC, CC, CC, CC, CC, proj_b, x, CC, 1.0f);

    // 5) LN2 -> bf16 pair
    ln_kernel<<<ROWS, 256>>>(x1, ln2_w, ln2_b, h2H, h2L);

    // 6) fc1 = gelu(...) -> bf16 pair
    gemm_bf<128,1,1><<<dim3(HID_/128, (ROWS+127)/128, 1), 256, SMEM128>>>(
        h2H, h2L, fc1wH, fc1wL, nullptr, fc1H, fc1L,
        ROWS, HID_, CC, CC, CC, HID_, fc1_b, nullptr, 0, 1.0f);

    // 7) out = x1 + fc1 @ fc2_w^T + fc2_b
    gemm_bf<128,2,0><<<dim3(CC/128, (ROWS+127)/128, 1), 256, SMEM128>>>(
        fc1H, fc1L, fc2wH, fc2wL, out_x, nullptr, nullptr,
        ROWS, CC, HID_, HID_, HID_, CC, fc2_b, x1, CC, 1.0f);
}

// round 9
// speedup vs baseline: 1.1408x; 1.1408x over previous
#include <cuda_runtime.h>
#include <cuda_bf16.h>
#include <math.h>
#include <stdint.h>

typedef unsigned short u16;

// Problem constants
#define BB   32
#define NN_  577
#define CC   768
#define HH_  12
#define DD   64
#define HID_ 3072
#define ROWS (BB*NN_)                    // 18464
#define ALPHA_ 0.1f
#define EPS_ 1e-6f
#define SCALE_ 0.125f

// ---------------- scratch --------------------------------------------------
__device__ u16 g_hlnH[(long long)ROWS*CC],  g_hlnL[(long long)ROWS*CC];
__device__ u16 g_qkvwH[(long long)3*CC*CC], g_qkvwL[(long long)3*CC*CC];
__device__ u16 g_projwH[(long long)CC*CC],  g_projwL[(long long)CC*CC];
__device__ u16 g_fc1wH[(long long)HID_*CC], g_fc1wL[(long long)HID_*CC];
__device__ u16 g_fc2wH[(long long)CC*HID_], g_fc2wL[(long long)CC*HID_];
__device__ u16 g_qkvH[(long long)ROWS*3*CC], g_qkvL[(long long)ROWS*3*CC];
__device__ u16 g_aoutH[(long long)ROWS*CC], g_aoutL[(long long)ROWS*CC];
__device__ float g_x1[(long long)ROWS*CC];
__device__ u16 g_h2H[(long long)ROWS*CC],  g_h2L[(long long)ROWS*CC];
__device__ u16 g_fc1H[(long long)ROWS*HID_], g_fc1L[(long long)ROWS*HID_];

// =================== asm helpers ===========================================
#define MMA16816(d, a0,a1,a2,a3, b0,b1) \
    asm volatile("mma.sync.aligned.m16n8k16.row.col.f32.bf16.bf16.f32 " \
        "{%0,%1,%2,%3}, {%4,%5,%6,%7}, {%8,%9}, {%0,%1,%2,%3};" \
        : "+f"((d)[0]), "+f"((d)[1]), "+f"((d)[2]), "+f"((d)[3]) \
        : "r"(a0), "r"(a1), "r"(a2), "r"(a3), "r"(b0), "r"(b1))

#define LDSM4(r, ad) \
    asm volatile("ldmatrix.sync.aligned.m8n8.x4.shared.b16 {%0,%1,%2,%3}, [%4];" \
        : "=r"((r)[0]), "=r"((r)[1]), "=r"((r)[2]), "=r"((r)[3]) : "r"(ad))

#define LDSM4T(r, ad) \
    asm volatile("ldmatrix.sync.aligned.m8n8.x4.trans.shared.b16 {%0,%1,%2,%3}, [%4];" \
        : "=r"((r)[0]), "=r"((r)[1]), "=r"((r)[2]), "=r"((r)[3]) : "r"(ad))

__device__ __forceinline__ void cpa16(uint32_t dst, const void* src, int sz) {
    asm volatile("cp.async.cg.shared.global [%0], [%1], 16, %2;" :: "r"(dst), "l"(src), "r"(sz) : "memory");
}
#define CP_COMMIT() asm volatile("cp.async.commit_group;" ::: "memory")
#define CP_WAIT1()  asm volatile("cp.async.wait_group 1;" ::: "memory")
#define CP_WAIT0()  asm volatile("cp.async.wait_group 0;" ::: "memory")

__device__ __forceinline__ uint32_t smem_u32(const void* p) {
    uint32_t a;
    asm("{ .reg .u64 t; cvta.to.shared.u64 t, %1; cvt.u32.u64 %0, t; }" : "=r"(a) : "l"(p));
    return a;
}
__device__ __forceinline__ uint32_t pack_bf2(float x, float y) {
    __nv_bfloat16 hx = __float2bfloat16_rn(x);
    __nv_bfloat16 hy = __float2bfloat16_rn(y);
    return ((uint32_t)__bfloat16_as_ushort(hy) << 16) | __bfloat16_as_ushort(hx);
}
__device__ __forceinline__ void split_bf(float v, u16& h, u16& l) {
    __nv_bfloat16 hb = __float2bfloat16_rn(v);
    h = __bfloat16_as_ushort(hb);
    l = __bfloat16_as_ushort(__float2bfloat16_rn(v - __bfloat162float(hb)));
}
__device__ __forceinline__ float bf_hi(float v) {
    return __bfloat162float(__float2bfloat16_rn(v));
}

// =================== bf16-pair HMMA GEMM (2-stage, 2 CTA/SM — R7 proven) ===
template<int BN, int EPI, int OUTB>
__global__ void __launch_bounds__(256, 2)
gemm_bf(const u16* __restrict__ AH, const u16* __restrict__ AL,
        const u16* __restrict__ BH, const u16* __restrict__ BL,
        float* __restrict__ C, u16* __restrict__ CH, u16* __restrict__ CL,
        int M, int N, int K, int ldA, int ldB, int ldC,
        const float* __restrict__ bias,
        const float* __restrict__ Res, int ldRes, float alpha)
{
    constexpr int ABYTES = 128 * 80;
    constexpr int BBYTES = BN * 80;
    constexpr int STAGE  = 2*ABYTES + 2*BBYTES;
    constexpr int NT     = BN / 16;
    constexpr int BCH    = BN / 64;

    const int tid = threadIdx.x, lane = tid & 31, wid = tid >> 5;
    const int gq = lane >> 2, tq = lane & 3;
    const int warp_m = wid & 3, warp_n = wid >> 2;

    const int rowBase = blockIdx.y * 128;
    const int colBase = blockIdx.x * BN;

    extern __shared__ char smraw[];
    const uint32_t smb = smem_u32(smraw);

    float acc[2][NT][4];
#pragma unroll
    for (int i = 0; i < 2; i++)
#pragma unroll
        for (int j = 0; j < NT; j++)
#pragma unroll
            for (int q = 0; q < 4; q++) acc[i][j][q] = 0.f;

    const int nst = K / 32;

    auto load_stage = [&](int s) {
        const int k0 = s * 32;
        const uint32_t base = smb + (s & 1) * STAGE;
#pragma unroll
        for (int i = 0; i < 2; i++) {
            int cid = tid + i*256;
            int row = cid >> 2, q = cid & 3;
            int gr = rowBase + row;
            int sz = (gr < M) ? 16 : 0;
            long long go = (long long)(gr < M ? gr : 0) * ldA + k0 + q*8;
            uint32_t so = row*80 + q*16;
            cpa16(base + so,          AH + go, sz);
            cpa16(base + ABYTES + so, AL + go, sz);
        }
#pragma unroll
        for (int i = 0; i < BCH; i++) {
            int cid = tid + i*256;
            int row = cid >> 2, q = cid & 3;
            int gn = colBase + row;
            int sz = (gn < N) ? 16 : 0;
            long long go = (long long)(gn < N ? gn : 0) * ldB + k0 + q*8;
            uint32_t so = row*80 + q*16;
            cpa16(base + 2*ABYTES + so,          BH + go, sz);
            cpa16(base + 2*ABYTES + BBYTES + so, BL + go, sz);
        }
    };

    const uint32_t lrow = lane & 15, lsel = lane >> 4;
    const uint32_t aOff = (warp_m*32 + lrow)*80 + lsel*16;
    const uint32_t bOff = (warp_n*(BN/2) + lrow)*80 + lsel*16;

    load_stage(0);
    CP_COMMIT();

    for (int s = 0; s < nst; s++) {
        if (s + 1 < nst) { load_stage(s + 1); CP_COMMIT(); CP_WAIT1(); }
        else             { CP_WAIT0(); }
        __syncthreads();

        const uint32_t st = smb + (s & 1) * STAGE;
#pragma unroll
        for (int ks = 0; ks < 2; ks++) {
            uint32_t ah[2][4], al[2][4];
#pragma unroll
            for (int i = 0; i < 2; i++) {
                LDSM4(ah[i], st + aOff + i*1280 + ks*32);
                LDSM4(al[i], st + ABYTES + aOff + i*1280 + ks*32);
            }
#pragma unroll
            for (int j2 = 0; j2 < NT/2; j2++) {
                uint32_t bh[4], bl[4];
                LDSM4(bh, st + 2*ABYTES + bOff + j2*1280 + ks*32);
                LDSM4(bl, st + 2*ABYTES + BBYTES + bOff + j2*1280 + ks*32);
#pragma unroll
                for (int i = 0; i < 2; i++) {
                    MMA16816(acc[i][2*j2],   ah[i][0],ah[i][1],ah[i][2],ah[i][3], bh[0], bh[2]);
                    MMA16816(acc[i][2*j2+1], ah[i][0],ah[i][1],ah[i][2],ah[i][3], bh[1], bh[3]);
                    MMA16816(acc[i][2*j2],   ah[i][0],ah[i][1],ah[i][2],ah[i][3], bl[0], bl[2]);
                    MMA16816(acc[i][2*j2+1], ah[i][0],ah[i][1],ah[i][2],ah[i][3], bl[1], bl[3]);
                    MMA16816(acc[i][2*j2],   al[i][0],al[i][1],al[i][2],al[i][3], bh[0], bh[2]);
                    MMA16816(acc[i][2*j2+1], al[i][0],al[i][1],al[i][2],al[i][3], bh[1], bh[3]);
                }
            }
        }
        __syncthreads();
    }

#pragma unroll
    for (int i = 0; i < 2; i++) {
#pragma unroll
        for (int half = 0; half < 2; half++) {
            const int r = rowBase + warp_m*32 + i*16 + gq + half*8;
            if (r >= M) continue;
#pragma unroll
            for (int j = 0; j < NT; j++) {
                const int c0 = colBase + warp_n*(BN/2) + j*8 + tq*2;
                float v0 = acc[i][j][half*2 + 0] * alpha;
                float v1 = acc[i][j][half*2 + 1] * alpha;
                if (bias) { v0 += bias[c0]; v1 += (c0+1 < N) ? bias[c0+1] : 0.f; }
                if (EPI == 1) {
                    v0 = 0.5f*v0*(1.0f + erff(v0*0.70710678118654752f));
                    v1 = 0.5f*v1*(1.0f + erff(v1*0.70710678118654752f));
                } else if (EPI == 2) {
                    v0 += Res[(long long)r*ldRes + c0];
                    if (c0+1 < N) v1 += Res[(long long)r*ldRes + c0 + 1];
                }
                if (OUTB) {
                    if (c0 + 1 < N) {
                        u16 h0,l0,h1,l1;
                        split_bf(v0, h0, l0); split_bf(v1, h1, l1);
                        *reinterpret_cast<uint32_t*>(CH + (long long)r*ldC + c0) = ((uint32_t)h1<<16)|h0;
                        *reinterpret_cast<uint32_t*>(CL + (long long)r*ldC + c0) = ((uint32_t)l1<<16)|l0;
                    } else if (c0 < N) {
                        u16 h0,l0; split_bf(v0, h0, l0);
                        CH[(long long)r*ldC + c0] = h0; CL[(long long)r*ldC + c0] = l0;
                    }
                } else {
                    if (c0 < N)     C[(long long)r*ldC + c0]     = v0;
                    if (c0+1 < N)   C[(long long)r*ldC + c0 + 1] = v1;
                }
            }
        }
    }
}

// =================== fused flash attention (R8 version, kept) ==============
// V loaded key-major directly from qkv; PV B-fragments via ldmatrix.trans.
#define QSTR 144
#define QHALF 18432            // 128*144
#define KBASE (2*QHALF)        // 36864
#define KSTG  (2*QHALF)
#define VBASE (KBASE + 2*KSTG) // 110592
#define VSTG  (2*QHALF)
#define FLASH_SMEM (VBASE + 2*VSTG)   // 184320

__global__ void __launch_bounds__(256, 1)
flash_attn(const u16* __restrict__ qkvH, const u16* __restrict__ qkvL,
           const float* __restrict__ attn_w,
           u16* __restrict__ aoutH, u16* __restrict__ aoutL,
           float* __restrict__ patch_out)
{
    const int z = blockIdx.y, qt = blockIdx.x;
    const int b = z / HH_, h = z % HH_;
    const int tid = threadIdx.x, lane = tid & 31, wid = tid >> 5;
    const int gq = lane >> 2, tq = lane & 3;

    extern __shared__ char smraw[];
    const uint32_t smb = smem_u32(smraw);

    // ---- load Q tile (once) ----
#pragma unroll
    for (int i = 0; i < 4; i++) {
        int cid = tid + i*256;
        int row = cid >> 3, ch = cid & 7;
        int gr = qt*128 + row;
        int sz = (gr < NN_) ? 16 : 0;
        long long go = (long long)(b*NN_ + (gr < NN_ ? gr : 0))*(3*CC) + h*DD + ch*8;
        cpa16(smb + row*QSTR + ch*16,         qkvH + go, sz);
        cpa16(smb + QHALF + row*QSTR + ch*16, qkvL + go, sz);
    }
    auto load_kv = [&](int t) {
        const uint32_t kb = smb + KBASE + (t & 1)*KSTG;
        const uint32_t vb = smb + VBASE + (t & 1)*VSTG;
#pragma unroll
        for (int i = 0; i < 4; i++) {
            int cid = tid + i*256;
            int row = cid >> 3, ch = cid & 7;
            int gk = t*128 + row;
            int sz = (gk < NN_) ? 16 : 0;
            long long base = (long long)(b*NN_ + (gk < NN_ ? gk : 0))*(3*CC) + h*DD + ch*8;
            cpa16(kb + row*QSTR + ch*16,         qkvH + base + CC, sz);
            cpa16(kb + QHALF + row*QSTR + ch*16, qkvL + base + CC, sz);
            cpa16(vb + row*QSTR + ch*16,         qkvH + base + 2*CC, sz);
            cpa16(vb + QHALF + row*QSTR + ch*16, qkvL + base + 2*CC, sz);
        }
    };

    float o[8][4];
#pragma unroll
    for (int j = 0; j < 8; j++)
#pragma unroll
        for (int q = 0; q < 4; q++) o[j][q] = 0.f;
    float m0 = -INFINITY, m1 = -INFINITY, l0 = 0.f, l1 = 0.f;

    const uint32_t lrow = lane & 15, lsel = lane >> 4;
    const uint32_t qOff = (wid*16 + lrow)*QSTR + lsel*16;
    const bool clsrow = (qt == 0) && (wid == 0) && (gq == 0);

    load_kv(0);
    CP_COMMIT();

    for (int t = 0; t < 5; t++) {
        if (t < 4) { load_kv(t + 1); CP_COMMIT(); CP_WAIT1(); }
        else       { CP_WAIT0(); }
        __syncthreads();

        const uint32_t kb = smb + KBASE + (t & 1)*KSTG;
        const uint32_t vb = smb + VBASE + (t & 1)*VSTG;

        // ---- S = Q @ K^T ----
        float s[16][4];
#pragma unroll
        for (int j = 0; j < 16; j++)
#pragma unroll
            for (int q = 0; q < 4; q++) s[j][q] = 0.f;

#pragma unroll
        for (int kg = 0; kg < 4; kg++) {
            uint32_t qh[4], ql[4];
            LDSM4(qh, smb + qOff + kg*32);
            LDSM4(ql, smb + QHALF + qOff + kg*32);
#pragma unroll
            for (int jj = 0; jj < 8; jj++) {
                uint32_t kh[4], kl[4];
                uint32_t ko = kb + (jj*16 + lrow)*QSTR + lsel*16 + kg*32;
                LDSM4(kh, ko);
                LDSM4(kl, ko + QHALF);
                MMA16816(s[2*jj],   qh[0],qh[1],qh[2],qh[3], kh[0], kh[2]);
                MMA16816(s[2*jj+1], qh[0],qh[1],qh[2],qh[3], kh[1], kh[3]);
                MMA16816(s[2*jj],   qh[0],qh[1],qh[2],qh[3], kl[0], kl[2]);
                MMA16816(s[2*jj+1], qh[0],qh[1],qh[2],qh[3], kl[1], kl[3]);
                MMA16816(s[2*jj],   ql[0],ql[1],ql[2],ql[3], kh[0], kh[2]);
                MMA16816(s[2*jj+1], ql[0],ql[1],ql[2],ql[3], kh[1], kh[3]);
            }
        }

        // ---- scale + CLS factor + patch + mask ----
#pragma unroll
        for (int jj = 0; jj < 16; jj++) {
#pragma unroll
            for (int qi = 0; qi < 4; qi++) {
                float v = s[jj][qi] * SCALE_;
                int key = t*128 + jj*8 + tq*2 + (qi & 1);
                if (clsrow && qi < 2) {
                    if (key >= 1 && key < NN_) {
                        patch_out[(long long)z*(NN_-1) + key - 1] = v;
                        v *= attn_w[(long long)b*(NN_-1) + key - 1] * ALPHA_ + (1.0f - ALPHA_);
                    }
                }
                if (key >= NN_) v = -1e30f;
                s[jj][qi] = v;
            }
        }

        // ---- online softmax ----
        float mx0 = -1e30f, mx1 = -1e30f;
#pragma unroll
        for (int jj = 0; jj < 16; jj++) {
            mx0 = fmaxf(mx0, fmaxf(s[jj][0], s[jj][1]));
            mx1 = fmaxf(mx1, fmaxf(s[jj][2], s[jj][3]));
        }
        mx0 = fmaxf(mx0, __shfl_xor_sync(~0u, mx0, 1)); mx0 = fmaxf(mx0, __shfl_xor_sync(~0u, mx0, 2));
        mx1 = fmaxf(mx1, __shfl_xor_sync(~0u, mx1, 1)); mx1 = fmaxf(mx1, __shfl_xor_sync(~0u, mx1, 2));
        float mn0 = fmaxf(m0, mx0), mn1 = fmaxf(m1, mx1);
        float f0 = __expf(m0 - mn0), f1 = __expf(m1 - mn1);
        m0 = mn0; m1 = mn1;
        float rs0 = 0.f, rs1 = 0.f;
#pragma unroll
        for (int jj = 0; jj < 16; jj++) {
            float p0 = __expf(s[jj][0] - m0), p1 = __expf(s[jj][1] - m0);
            float p2 = __expf(s[jj][2] - m1), p3 = __expf(s[jj][3] - m1);
            s[jj][0] = p0; s[jj][1] = p1; s[jj][2] = p2; s[jj][3] = p3;
            rs0 += p0 + p1; rs1 += p2 + p3;
        }
        rs0 += __shfl_xor_sync(~0u, rs0, 1); rs0 += __shfl_xor_sync(~0u, rs0, 2);
        rs1 += __shfl_xor_sync(~0u, rs1, 1); rs1 += __shfl_xor_sync(~0u, rs1, 2);
        l0 = l0*f0 + rs0; l1 = l1*f1 + rs1;
#pragma unroll
        for (int j = 0; j < 8; j++) {
            o[j][0] *= f0; o[j][1] *= f0; o[j][2] *= f1; o[j][3] *= f1;
        }

        // ---- O += P @ V (V key-major, trans ldmatrix) ----
#pragma unroll
        for (int kg = 0; kg < 8; kg++) {
            uint32_t ah[4], al[4];
            {
                float v00 = s[2*kg][0],   v01 = s[2*kg][1],   v02 = s[2*kg][2],   v03 = s[2*kg][3];
                float v10 = s[2*kg+1][0], v11 = s[2*kg+1][1], v12 = s[2*kg+1][2], v13 = s[2*kg+1][3];
                ah[0] = pack_bf2(v00, v01); ah[1] = pack_bf2(v02, v03);
                ah[2] = pack_bf2(v10, v11); ah[3] = pack_bf2(v12, v13);
                al[0] = pack_bf2(v00 - bf_hi(v00), v01 - bf_hi(v01));
                al[1] = pack_bf2(v02 - bf_hi(v02), v03 - bf_hi(v03));
                al[2] = pack_bf2(v10 - bf_hi(v10), v11 - bf_hi(v11));
                al[3] = pack_bf2(v12 - bf_hi(v12), v13 - bf_hi(v13));
            }
#pragma unroll
            for (int jp = 0; jp < 4; jp++) {
                uint32_t vh[4], vl[4];
                uint32_t vo = vb + (kg*16 + lrow)*QSTR + jp*32 + lsel*16;
                LDSM4T(vh, vo);
                LDSM4T(vl, vo + QHALF);
                MMA16816(o[2*jp],   ah[0],ah[1],ah[2],ah[3], vh[0], vh[1]);
                MMA16816(o[2*jp+1], ah[0],ah[1],ah[2],ah[3], vh[2], vh[3]);
                MMA16816(o[2*jp],   ah[0],ah[1],ah[2],ah[3], vl[0], vl[1]);
                MMA16816(o[2*jp+1], ah[0],ah[1],ah[2],ah[3], vl[2], vl[3]);
                MMA16816(o[2*jp],   al[0],al[1],al[2],al[3], vh[0], vh[1]);
                MMA16816(o[2*jp+1], al[0],al[1],al[2],al[3], vh[2], vh[3]);
            }
        }
        __syncthreads();
    }

    // ---- epilogue ----
    const float inv0 = 1.0f / l0, inv1 = 1.0f / l1;
    const int q0 = qt*128 + wid*16 + gq, q1 = q0 + 8;
#pragma unroll
    for (int j = 0; j < 8; j++) {
        int d0 = j*8 + tq*2;
        if (q0 < NN_) {
            float v0 = o[j][0]*inv0, v1 = o[j][1]*inv0;
            u16 h0,lw0,h1,lw1; split_bf(v0,h0,lw0); split_bf(v1,h1,lw1);
            long long off = (long long)(b*NN_ + q0)*CC + h*DD + d0;
            *reinterpret_cast<uint32_t*>(aoutH + off) = ((uint32_t)h1<<16)|h0;
            *reinterpret_cast<uint32_t*>(aoutL + off) = ((uint32_t)lw1<<16)|lw0;
        }
        if (q1 < NN_) {
            float v0 = o[j][2]*inv1, v1 = o[j][3]*inv1;
            u16 h0,lw0,h1,lw1; split_bf(v0,h0,lw0); split_bf(v1,h1,lw1);
            long long off = (long long)(b*NN_ + q1)*CC + h*DD + d0;
            *reinterpret_cast<uint32_t*>(aoutH + off) = ((uint32_t)h1<<16)|h0;
            *reinterpret_cast<uint32_t*>(aoutL + off) = ((uint32_t)lw1<<16)|lw0;
        }
    }
}

// ---------------- weight fp32 -> bf16 hi/lo --------------------------------
__global__ void conv_pair(const float* __restrict__ src, u16* __restrict__ hi,
                          u16* __restrict__ lo, long long n4)
{
    long long i = (long long)blockIdx.x * blockDim.x + threadIdx.x;
    if (i >= n4) return;
    float4 v = reinterpret_cast<const float4*>(src)[i];
    u16 h0,l0,h1,l1,h2,l2,h3,l3;
    split_bf(v.x,h0,l0); split_bf(v.y,h1,l1); split_bf(v.z,h2,l2); split_bf(v.w,h3,l3);
    uint2 hp = { ((uint32_t)h1<<16)|h0, ((uint32_t)h3<<16)|h2 };
    uint2 lp = { ((uint32_t)l1<<16)|l0, ((uint32_t)l3<<16)|l2 };
    reinterpret_cast<uint2*>(hi)[i] = hp;
    reinterpret_cast<uint2*>(lo)[i] = lp;
}

// ---------------- LayerNorm -> bf16 hi/lo ----------------------------------
__global__ void ln_kernel(const float* __restrict__ in,
                          const float* __restrict__ w, const float* __restrict__ b,
                          u16* __restrict__ outH, u16* __restrict__ outL)
{
    const long long row = blockIdx.x;
    const int tid = threadIdx.x;
    const float* rp = in + row * CC;
    float v0 = rp[tid], v1 = rp[tid+256], v2 = rp[tid+512];
    float s = v0+v1+v2, ss = v0*v0 + v1*v1 + v2*v2;
    const int wid = tid >> 5, lid = tid & 31;
    for (int o = 16; o; o >>= 1) { s += __shfl_xor_sync(~0u, s, o); ss += __shfl_xor_sync(~0u, ss, o); }
    __shared__ float rs[8], rq[8];
    if (lid == 0) { rs[wid] = s; rq[wid] = ss; }
    __syncthreads();
    float ts = 0.f, tq = 0.f;
#pragma unroll
    for (int i = 0; i < 8; i++) { ts += rs[i]; tq += rq[i]; }
    float mean = ts * (1.0f/CC);
    float rstd = rsqrtf(tq * (1.0f/CC) - mean*mean + EPS_);
#pragma unroll
    for (int k = 0; k < 3; k++) {
        int c = tid + k*256;
        float v = (k==0?v0:(k==1?v1:v2));
        float y = (v - mean)*rstd * w[c] + b[c];
        u16 h,l; split_bf(y,h,l);
        outH[row*CC + c] = h; outL[row*CC + c] = l;
    }
}

// ---------------------------------------------------------------------------
extern "C" void kernel_launch(void* const* d_in, const int* in_sizes, int n_in,
                              void* d_out, int out_size)
{
    const float* x      = (const float*)d_in[0];
    const float* attn_w = (const float*)d_in[1];
    const float* ln1_w  = (const float*)d_in[2];
    const float* ln1_b  = (const float*)d_in[3];
    const float* qkv_w  = (const float*)d_in[4];
    const float* qkv_b  = (const float*)d_in[5];
    const float* proj_w = (const float*)d_in[6];
    const float* proj_b = (const float*)d_in[7];
    const float* ln2_w  = (const float*)d_in[8];
    const float* ln2_b  = (const float*)d_in[9];
    const float* fc1_w  = (const float*)d_in[10];
    const float* fc1_b  = (const float*)d_in[11];
    const float* fc2_w  = (const float*)d_in[12];
    const float* fc2_b  = (const float*)d_in[13];

    float* out_x     = (float*)d_out;
    float* out_patch = out_x + (long long)ROWS*CC;

    u16 *hlnH,*hlnL,*qkvwH,*qkvwL,*projwH,*projwL,*fc1wH,*fc1wL,*fc2wH,*fc2wL;
    u16 *qkvH,*qkvL,*aoutH,*aoutL,*h2H,*h2L,*fc1H,*fc1L;
    float *x1;
    cudaGetSymbolAddress((void**)&hlnH, g_hlnH);   cudaGetSymbolAddress((void**)&hlnL, g_hlnL);
    cudaGetSymbolAddress((void**)&qkvwH, g_qkvwH); cudaGetSymbolAddress((void**)&qkvwL, g_qkvwL);
    cudaGetSymbolAddress((void**)&projwH, g_projwH); cudaGetSymbolAddress((void**)&projwL, g_projwL);
    cudaGetSymbolAddress((void**)&fc1wH, g_fc1wH); cudaGetSymbolAddress((void**)&fc1wL, g_fc1wL);
    cudaGetSymbolAddress((void**)&fc2wH, g_fc2wH); cudaGetSymbolAddress((void**)&fc2wL, g_fc2wL);
    cudaGetSymbolAddress((void**)&qkvH, g_qkvH);   cudaGetSymbolAddress((void**)&qkvL, g_qkvL);
    cudaGetSymbolAddress((void**)&aoutH, g_aoutH); cudaGetSymbolAddress((void**)&aoutL, g_aoutL);
    cudaGetSymbolAddress((void**)&x1, g_x1);
    cudaGetSymbolAddress((void**)&h2H, g_h2H);     cudaGetSymbolAddress((void**)&h2L, g_h2L);
    cudaGetSymbolAddress((void**)&fc1H, g_fc1H);   cudaGetSymbolAddress((void**)&fc1L, g_fc1L);

    const int SMEM128 = 2 * (2*128*80 + 2*128*80);   // 81920
    cudaFuncSetAttribute(gemm_bf<128,0,1>, cudaFuncAttributeMaxDynamicSharedMemorySize, SMEM128);
    cudaFuncSetAttribute(gemm_bf<128,1,1>, cudaFuncAttributeMaxDynamicSharedMemorySize, SMEM128);
    cudaFuncSetAttribute(gemm_bf<128,2,0>, cudaFuncAttributeMaxDynamicSharedMemorySize, SMEM128);
    cudaFuncSetAttribute(flash_attn, cudaFuncAttributeMaxDynamicSharedMemorySize, FLASH_SMEM);

    // 0) weight conversions
    conv_pair<<<(int)(((long long)3*CC*CC/4 + 255)/256), 256>>>(qkv_w,  qkvwH,  qkvwL,  (long long)3*CC*CC/4);
    conv_pair<<<(int)(((long long)CC*CC/4   + 255)/256), 256>>>(proj_w, projwH, projwL, (long long)CC*CC/4);
    conv_pair<<<(int)(((long long)HID_*CC/4 + 255)/256), 256>>>(fc1_w,  fc1wH,  fc1wL,  (long long)HID_*CC/4);
    conv_pair<<<(int)(((long long)CC*HID_/4 + 255)/256), 256>>>(fc2_w,  fc2wH,  fc2wL,  (long long)CC*HID_/4);

    // 1) LN1 -> bf16 pair
    ln_kernel<<<ROWS, 256>>>(x, ln1_w, ln1_b, hlnH, hlnL);

    // 2) qkv GEMM -> bf16 pair
    gemm_bf<128,0,1><<<dim3(3*CC/128, (ROWS+127)/128, 1), 256, SMEM128>>>(
        hlnH, hlnL, qkvwH, qkvwL, nullptr, qkvH, qkvL,
        ROWS, 3*CC, CC, CC, CC, 3*CC, qkv_b, nullptr, 0, 1.0f);

    // 3) fused flash attention
    flash_attn<<<dim3(5, BB*HH_), 256, FLASH_SMEM>>>(
        qkvH, qkvL, attn_w, aoutH, aoutL, out_patch);

    // 4) x1 = x + aout @ proj_w^T + proj_b
    gemm_bf<128,2,0><<<dim3(CC/128, (ROWS+127)/128, 1), 256, SMEM128>>>(
        aoutH, aoutL, projwH, projwL, x1, nullptr, nullptr,
        ROWS, CC, CC, CC, CC, CC, proj_b, x, CC, 1.0f);

    // 5) LN2 -> bf16 pair
    ln_kernel<<<ROWS, 256>>>(x1, ln2_w, ln2_b, h2H, h2L);

    // 6) fc1 = gelu(...) -> bf16 pair
    gemm_bf<128,1,1><<<dim3(HID_/128, (ROWS+127)/128, 1), 256, SMEM128>>>(
        h2H, h2L, fc1wH, fc1wL, nullptr, fc1H, fc1L,
        ROWS, HID_, CC, CC, CC, HID_, fc1_b, nullptr, 0, 1.0f);

    // 7) out = x1 + fc1 @ fc2_w^T + fc2_b
    gemm_bf<128,2,0><<<dim3(CC/128, (ROWS+127)/128, 1), 256, SMEM128>>>(
        fc1H, fc1L, fc2wH, fc2wL, out_x, nullptr, nullptr,
        ROWS, CC, HID_, HID_, HID_, CC, fc2_b, x1, CC, 1.0f);
}

// round 11
// speedup vs baseline: 1.7760x; 1.5568x over previous
#include <cuda_runtime.h>
#include <cuda_bf16.h>
#include <cuda_fp16.h>
#include <math.h>
#include <stdint.h>

typedef unsigned short u16;

// Problem constants
#define BB   32
#define NN_  577
#define CC   768
#define HH_  12
#define DD   64
#define HID_ 3072
#define ROWS (BB*NN_)                    // 18464
#define ALPHA_ 0.1f
#define EPS_ 1e-6f
#define SCALE_ 0.125f

// ---------------- scratch --------------------------------------------------
__device__ u16 g_hlnH[(long long)ROWS*CC],  g_hlnL[(long long)ROWS*CC];
__device__ u16 g_qkvwH[(long long)3*CC*CC], g_qkvwL[(long long)3*CC*CC];
__device__ __half g_projwF[(long long)CC*CC];
__device__ __half g_fc1wF[(long long)HID_*CC];
__device__ __half g_fc2wF[(long long)CC*HID_];
__device__ u16 g_qkvH[(long long)ROWS*3*CC], g_qkvL[(long long)ROWS*3*CC];
__device__ __half g_aoutF[(long long)ROWS*CC];
__device__ float g_x1[(long long)ROWS*CC];
__device__ __half g_h2F[(long long)ROWS*CC];
__device__ __half g_fc1F[(long long)ROWS*HID_];

// =================== asm helpers ===========================================
#define MMA16816(d, a0,a1,a2,a3, b0,b1) \
    asm volatile("mma.sync.aligned.m16n8k16.row.col.f32.bf16.bf16.f32 " \
        "{%0,%1,%2,%3}, {%4,%5,%6,%7}, {%8,%9}, {%0,%1,%2,%3};" \
        : "+f"((d)[0]), "+f"((d)[1]), "+f"((d)[2]), "+f"((d)[3]) \
        : "r"(a0), "r"(a1), "r"(a2), "r"(a3), "r"(b0), "r"(b1))

#define MMAH16816(d, a0,a1,a2,a3, b0,b1) \
    asm volatile("mma.sync.aligned.m16n8k16.row.col.f32.f16.f16.f32 " \
        "{%0,%1,%2,%3}, {%4,%5,%6,%7}, {%8,%9}, {%0,%1,%2,%3};" \
        : "+f"((d)[0]), "+f"((d)[1]), "+f"((d)[2]), "+f"((d)[3]) \
        : "r"(a0), "r"(a1), "r"(a2), "r"(a3), "r"(b0), "r"(b1))

#define LDSM4(r, ad) \
    asm volatile("ldmatrix.sync.aligned.m8n8.x4.shared.b16 {%0,%1,%2,%3}, [%4];" \
        : "=r"((r)[0]), "=r"((r)[1]), "=r"((r)[2]), "=r"((r)[3]) : "r"(ad))

#define LDSM4T(r, ad) \
    asm volatile("ldmatrix.sync.aligned.m8n8.x4.trans.shared.b16 {%0,%1,%2,%3}, [%4];" \
        : "=r"((r)[0]), "=r"((r)[1]), "=r"((r)[2]), "=r"((r)[3]) : "r"(ad))

__device__ __forceinline__ void cpa16(uint32_t dst, const void* src, int sz) {
    asm volatile("cp.async.cg.shared.global [%0], [%1], 16, %2;" :: "r"(dst), "l"(src), "r"(sz) : "memory");
}
#define CP_COMMIT() asm volatile("cp.async.commit_group;" ::: "memory")
#define CP_WAIT1()  asm volatile("cp.async.wait_group 1;" ::: "memory")
#define CP_WAIT0()  asm volatile("cp.async.wait_group 0;" ::: "memory")

__device__ __forceinline__ uint32_t smem_u32(const void* p) {
    uint32_t a;
    asm("{ .reg .u64 t; cvta.to.shared.u64 t, %1; cvt.u32.u64 %0, t; }" : "=r"(a) : "l"(p));
    return a;
}
__device__ __forceinline__ uint32_t pack_bf2(float x, float y) {
    __nv_bfloat16 hx = __float2bfloat16_rn(x);
    __nv_bfloat16 hy = __float2bfloat16_rn(y);
    return ((uint32_t)__bfloat16_as_ushort(hy) << 16) | __bfloat16_as_ushort(hx);
}
__device__ __forceinline__ void split_bf(float v, u16& h, u16& l) {
    __nv_bfloat16 hb = __float2bfloat16_rn(v);
    h = __bfloat16_as_ushort(hb);
    l = __bfloat16_as_ushort(__float2bfloat16_rn(v - __bfloat162float(hb)));
}
__device__ __forceinline__ float bf_hi(float v) {
    return __bfloat162float(__float2bfloat16_rn(v));
}

// =================== bf16-pair HMMA GEMM (qkv only) ========================
template<int BN, int EPI, int OUTB>
__global__ void __launch_bounds__(256, 2)
gemm_bf(const u16* __restrict__ AH, const u16* __restrict__ AL,
        const u16* __restrict__ BH, const u16* __restrict__ BL,
        float* __restrict__ C, u16* __restrict__ CH, u16* __restrict__ CL,
        int M, int N, int K, int ldA, int ldB, int ldC,
        const float* __restrict__ bias,
        const float* __restrict__ Res, int ldRes, float alpha)
{
    constexpr int ABYTES = 128 * 80;
    constexpr int BBYTES = BN * 80;
    constexpr int STAGE  = 2*ABYTES + 2*BBYTES;
    constexpr int NT     = BN / 16;
    constexpr int BCH    = BN / 64;

    const int tid = threadIdx.x, lane = tid & 31, wid = tid >> 5;
    const int gq = lane >> 2, tq = lane & 3;
    const int warp_m = wid & 3, warp_n = wid >> 2;

    const int rowBase = blockIdx.y * 128;
    const int colBase = blockIdx.x * BN;

    extern __shared__ char smraw[];
    const uint32_t smb = smem_u32(smraw);

    float acc[2][NT][4];
#pragma unroll
    for (int i = 0; i < 2; i++)
#pragma unroll
        for (int j = 0; j < NT; j++)
#pragma unroll
            for (int q = 0; q < 4; q++) acc[i][j][q] = 0.f;

    const int nst = K / 32;

    auto load_stage = [&](int s) {
        const int k0 = s * 32;
        const uint32_t base = smb + (s & 1) * STAGE;
#pragma unroll
        for (int i = 0; i < 2; i++) {
            int cid = tid + i*256;
            int row = cid >> 2, q = cid & 3;
            int gr = rowBase + row;
            int sz = (gr < M) ? 16 : 0;
            long long go = (long long)(gr < M ? gr : 0) * ldA + k0 + q*8;
            uint32_t so = row*80 + q*16;
            cpa16(base + so,          AH + go, sz);
            cpa16(base + ABYTES + so, AL + go, sz);
        }
#pragma unroll
        for (int i = 0; i < BCH; i++) {
            int cid = tid + i*256;
            int row = cid >> 2, q = cid & 3;
            int gn = colBase + row;
            int sz = (gn < N) ? 16 : 0;
            long long go = (long long)(gn < N ? gn : 0) * ldB + k0 + q*8;
            uint32_t so = row*80 + q*16;
            cpa16(base + 2*ABYTES + so,          BH + go, sz);
            cpa16(base + 2*ABYTES + BBYTES + so, BL + go, sz);
        }
    };

    const uint32_t lrow = lane & 15, lsel = lane >> 4;
    const uint32_t aOff = (warp_m*32 + lrow)*80 + lsel*16;
    const uint32_t bOff = (warp_n*(BN/2) + lrow)*80 + lsel*16;

    load_stage(0);
    CP_COMMIT();

    for (int s = 0; s < nst; s++) {
        if (s + 1 < nst) { load_stage(s + 1); CP_COMMIT(); CP_WAIT1(); }
        else             { CP_WAIT0(); }
        __syncthreads();

        const uint32_t st = smb + (s & 1) * STAGE;
#pragma unroll
        for (int ks = 0; ks < 2; ks++) {
            uint32_t ah[2][4], al[2][4];
#pragma unroll
            for (int i = 0; i < 2; i++) {
                LDSM4(ah[i], st + aOff + i*1280 + ks*32);
                LDSM4(al[i], st + ABYTES + aOff + i*1280 + ks*32);
            }
#pragma unroll
            for (int j2 = 0; j2 < NT/2; j2++) {
                uint32_t bh[4], bl[4];
                LDSM4(bh, st + 2*ABYTES + bOff + j2*1280 + ks*32);
                LDSM4(bl, st + 2*ABYTES + BBYTES + bOff + j2*1280 + ks*32);
#pragma unroll
                for (int i = 0; i < 2; i++) {
                    MMA16816(acc[i][2*j2],   ah[i][0],ah[i][1],ah[i][2],ah[i][3], bh[0], bh[2]);
                    MMA16816(acc[i][2*j2+1], ah[i][0],ah[i][1],ah[i][2],ah[i][3], bh[1], bh[3]);
                    MMA16816(acc[i][2*j2],   ah[i][0],ah[i][1],ah[i][2],ah[i][3], bl[0], bl[2]);
                    MMA16816(acc[i][2*j2+1], ah[i][0],ah[i][1],ah[i][2],ah[i][3], bl[1], bl[3]);
                    MMA16816(acc[i][2*j2],   al[i][0],al[i][1],al[i][2],al[i][3], bh[0], bh[2]);
                    MMA16816(acc[i][2*j2+1], al[i][0],al[i][1],al[i][2],al[i][3], bh[1], bh[3]);
                }
            }
        }
        __syncthreads();
    }

#pragma unroll
    for (int i = 0; i < 2; i++) {
#pragma unroll
        for (int half = 0; half < 2; half++) {
            const int r = rowBase + warp_m*32 + i*16 + gq + half*8;
            if (r >= M) continue;
#pragma unroll
            for (int j = 0; j < NT; j++) {
                const int c0 = colBase + warp_n*(BN/2) + j*8 + tq*2;
                float v0 = acc[i][j][half*2 + 0] * alpha;
                float v1 = acc[i][j][half*2 + 1] * alpha;
                if (bias) { v0 += bias[c0]; v1 += (c0+1 < N) ? bias[c0+1] : 0.f; }
                if (EPI == 2) {
                    v0 += Res[(long long)r*ldRes + c0];
                    if (c0+1 < N) v1 += Res[(long long)r*ldRes + c0 + 1];
                }
                if (OUTB) {
                    if (c0 + 1 < N) {
                        u16 h0,l0,h1,l1;
                        split_bf(v0, h0, l0); split_bf(v1, h1, l1);
                        *reinterpret_cast<uint32_t*>(CH + (long long)r*ldC + c0) = ((uint32_t)h1<<16)|h0;
                        *reinterpret_cast<uint32_t*>(CL + (long long)r*ldC + c0) = ((uint32_t)l1<<16)|l0;
                    } else if (c0 < N) {
                        u16 h0,l0; split_bf(v0, h0, l0);
                        CH[(long long)r*ldC + c0] = h0; CL[(long long)r*ldC + c0] = l0;
                    }
                } else {
                    if (c0 < N)     C[(long long)r*ldC + c0]     = v0;
                    if (c0+1 < N)   C[(long long)r*ldC + c0 + 1] = v1;
                }
            }
        }
    }
}

// =================== single-pass fp16 HMMA GEMM (proj, fc1, fc2) ===========
// EPI: 0 none, 1 exact GELU, 2 +Res.  OUTF: 0 fp32 C, 1 fp16 CF.
template<int BN, int EPI, int OUTF>
__global__ void __launch_bounds__(256, 2)
gemm_hf(const __half* __restrict__ A, const __half* __restrict__ B,
        float* __restrict__ C, __half* __restrict__ CF,
        int M, int N, int K, int ldA, int ldB, int ldC,
        const float* __restrict__ bias,
        const float* __restrict__ Res, int ldRes)
{
    constexpr int ABYTES = 128 * 80;
    constexpr int BBYTES = BN * 80;
    constexpr int STAGE  = ABYTES + BBYTES;      // 20480 for BN=128
    constexpr int NT     = BN / 16;
    constexpr int BCH    = BN / 64;              // B passes: BN rows * 4 chunks / 256 thr

    const int tid = threadIdx.x, lane = tid & 31, wid = tid >> 5;
    const int gq = lane >> 2, tq = lane & 3;
    const int warp_m = wid & 3, warp_n = wid >> 2;

    const int rowBase = blockIdx.y * 128;
    const int colBase = blockIdx.x * BN;

    extern __shared__ char smraw[];
    const uint32_t smb = smem_u32(smraw);

    float acc[2][NT][4];
#pragma unroll
    for (int i = 0; i < 2; i++)
#pragma unroll
        for (int j = 0; j < NT; j++)
#pragma unroll
            for (int q = 0; q < 4; q++) acc[i][j][q] = 0.f;

    const int nst = K / 32;

    auto load_stage = [&](int s) {
        const int k0 = s * 32;
        const uint32_t base = smb + (s & 1) * STAGE;
#pragma unroll
        for (int i = 0; i < 2; i++) {
            int cid = tid + i*256;
            int row = cid >> 2, q = cid & 3;
            int gr = rowBase + row;
            int sz = (gr < M) ? 16 : 0;
            long long go = (long long)(gr < M ? gr : 0) * ldA + k0 + q*8;
            cpa16(base + row*80 + q*16, A + go, sz);
        }
#pragma unroll
        for (int i = 0; i < BCH; i++) {            // FIXED: was BCH*2 (OOB smem writes)
            int cid = tid + i*256;
            int row = cid >> 2, q = cid & 3;
            int gn = colBase + row;
            int sz = (gn < N) ? 16 : 0;
            long long go = (long long)(gn < N ? gn : 0) * ldB + k0 + q*8;
            cpa16(base + ABYTES + row*80 + q*16, B + go, sz);
        }
    };

    const uint32_t lrow = lane & 15, lsel = lane >> 4;
    const uint32_t aOff = (warp_m*32 + lrow)*80 + lsel*16;
    const uint32_t bOff = (warp_n*(BN/2) + lrow)*80 + lsel*16;

    load_stage(0);
    CP_COMMIT();

    for (int s = 0; s < nst; s++) {
        if (s + 1 < nst) { load_stage(s + 1); CP_COMMIT(); CP_WAIT1(); }
        else             { CP_WAIT0(); }
        __syncthreads();

        const uint32_t st = smb + (s & 1) * STAGE;
#pragma unroll
        for (int ks = 0; ks < 2; ks++) {
            uint32_t a[2][4];
#pragma unroll
            for (int i = 0; i < 2; i++)
                LDSM4(a[i], st + aOff + i*1280 + ks*32);
#pragma unroll
            for (int j2 = 0; j2 < NT/2; j2++) {
                uint32_t bf[4];
                LDSM4(bf, st + ABYTES + bOff + j2*1280 + ks*32);
#pragma unroll
                for (int i = 0; i < 2; i++) {
                    MMAH16816(acc[i][2*j2],   a[i][0],a[i][1],a[i][2],a[i][3], bf[0], bf[2]);
                    MMAH16816(acc[i][2*j2+1], a[i][0],a[i][1],a[i][2],a[i][3], bf[1], bf[3]);
                }
            }
        }
        __syncthreads();
    }

#pragma unroll
    for (int i = 0; i < 2; i++) {
#pragma unroll
        for (int half = 0; half < 2; half++) {
            const int r = rowBase + warp_m*32 + i*16 + gq + half*8;
            if (r >= M) continue;
#pragma unroll
            for (int j = 0; j < NT; j++) {
                const int c0 = colBase + warp_n*(BN/2) + j*8 + tq*2;
                float v0 = acc[i][j][half*2 + 0];
                float v1 = acc[i][j][half*2 + 1];
                if (bias) { v0 += bias[c0]; v1 += (c0+1 < N) ? bias[c0+1] : 0.f; }
                if (EPI == 1) {
                    v0 = 0.5f*v0*(1.0f + erff(v0*0.70710678118654752f));
                    v1 = 0.5f*v1*(1.0f + erff(v1*0.70710678118654752f));
                } else if (EPI == 2) {
                    v0 += Res[(long long)r*ldRes + c0];
                    if (c0+1 < N) v1 += Res[(long long)r*ldRes + c0 + 1];
                }
                if (OUTF) {
                    if (c0 + 1 < N) {
                        *reinterpret_cast<__half2*>(CF + (long long)r*ldC + c0) = __floats2half2_rn(v0, v1);
                    } else if (c0 < N) {
                        CF[(long long)r*ldC + c0] = __float2half_rn(v0);
                    }
                } else {
                    if (c0 < N)     C[(long long)r*ldC + c0]     = v0;
                    if (c0+1 < N)   C[(long long)r*ldC + c0 + 1] = v1;
                }
            }
        }
    }
}

// =================== fused flash attention (bf16x3, fp16 out) ==============
#define QSTR 144
#define QHALF 18432            // 128*144
#define KBASE (2*QHALF)        // 36864
#define KSTG  (2*QHALF)
#define VBASE (KBASE + 2*KSTG) // 110592
#define VSTG  (2*QHALF)
#define FLASH_SMEM (VBASE + 2*VSTG)   // 184320

__global__ void __launch_bounds__(256, 1)
flash_attn(const u16* __restrict__ qkvH, const u16* __restrict__ qkvL,
           const float* __restrict__ attn_w,
           __half* __restrict__ aoutF,
           float* __restrict__ patch_out)
{
    const int z = blockIdx.y, qt = blockIdx.x;
    const int b = z / HH_, h = z % HH_;
    const int tid = threadIdx.x, lane = tid & 31, wid = tid >> 5;
    const int gq = lane >> 2, tq = lane & 3;

    extern __shared__ char smraw[];
    const uint32_t smb = smem_u32(smraw);

#pragma unroll
    for (int i = 0; i < 4; i++) {
        int cid = tid + i*256;
        int row = cid >> 3, ch = cid & 7;
        int gr = qt*128 + row;
        int sz = (gr < NN_) ? 16 : 0;
        long long go = (long long)(b*NN_ + (gr < NN_ ? gr : 0))*(3*CC) + h*DD + ch*8;
        cpa16(smb + row*QSTR + ch*16,         qkvH + go, sz);
        cpa16(smb + QHALF + row*QSTR + ch*16, qkvL + go, sz);
    }
    auto load_kv = [&](int t) {
        const uint32_t kb = smb + KBASE + (t & 1)*KSTG;
        const uint32_t vb = smb + VBASE + (t & 1)*VSTG;
#pragma unroll
        for (int i = 0; i < 4; i++) {
            int cid = tid + i*256;
            int row = cid >> 3, ch = cid & 7;
            int gk = t*128 + row;
            int sz = (gk < NN_) ? 16 : 0;
            long long base = (long long)(b*NN_ + (gk < NN_ ? gk : 0))*(3*CC) + h*DD + ch*8;
            cpa16(kb + row*QSTR + ch*16,         qkvH + base + CC, sz);
            cpa16(kb + QHALF + row*QSTR + ch*16, qkvL + base + CC, sz);
            cpa16(vb + row*QSTR + ch*16,         qkvH + base + 2*CC, sz);
            cpa16(vb + QHALF + row*QSTR + ch*16, qkvL + base + 2*CC, sz);
        }
    };

    float o[8][4];
#pragma unroll
    for (int j = 0; j < 8; j++)
#pragma unroll
        for (int q = 0; q < 4; q++) o[j][q] = 0.f;
    float m0 = -INFINITY, m1 = -INFINITY, l0 = 0.f, l1 = 0.f;

    const uint32_t lrow = lane & 15, lsel = lane >> 4;
    const uint32_t qOff = (wid*16 + lrow)*QSTR + lsel*16;
    const bool clsrow = (qt == 0) && (wid == 0) && (gq == 0);

    load_kv(0);
    CP_COMMIT();

    for (int t = 0; t < 5; t++) {
        if (t < 4) { load_kv(t + 1); CP_COMMIT(); CP_WAIT1(); }
        else       { CP_WAIT0(); }
        __syncthreads();

        const uint32_t kb = smb + KBASE + (t & 1)*KSTG;
        const uint32_t vb = smb + VBASE + (t & 1)*VSTG;

        float s[16][4];
#pragma unroll
        for (int j = 0; j < 16; j++)
#pragma unroll
            for (int q = 0; q < 4; q++) s[j][q] = 0.f;

#pragma unroll
        for (int kg = 0; kg < 4; kg++) {
            uint32_t qh[4], ql[4];
            LDSM4(qh, smb + qOff + kg*32);
            LDSM4(ql, smb + QHALF + qOff + kg*32);
#pragma unroll
            for (int jj = 0; jj < 8; jj++) {
                uint32_t kh[4], kl[4];
                uint32_t ko = kb + (jj*16 + lrow)*QSTR + lsel*16 + kg*32;
                LDSM4(kh, ko);
                LDSM4(kl, ko + QHALF);
                MMA16816(s[2*jj],   qh[0],qh[1],qh[2],qh[3], kh[0], kh[2]);
                MMA16816(s[2*jj+1], qh[0],qh[1],qh[2],qh[3], kh[1], kh[3]);
                MMA16816(s[2*jj],   qh[0],qh[1],qh[2],qh[3], kl[0], kl[2]);
                MMA16816(s[2*jj+1], qh[0],qh[1],qh[2],qh[3], kl[1], kl[3]);
                MMA16816(s[2*jj],   ql[0],ql[1],ql[2],ql[3], kh[0], kh[2]);
                MMA16816(s[2*jj+1], ql[0],ql[1],ql[2],ql[3], kh[1], kh[3]);
            }
        }

#pragma unroll
        for (int jj = 0; jj < 16; jj++) {
#pragma unroll
            for (int qi = 0; qi < 4; qi++) {
                float v = s[jj][qi] * SCALE_;
                int key = t*128 + jj*8 + tq*2 + (qi & 1);
                if (clsrow && qi < 2) {
                    if (key >= 1 && key < NN_) {
                        patch_out[(long long)z*(NN_-1) + key - 1] = v;
                        v *= attn_w[(long long)b*(NN_-1) + key - 1] * ALPHA_ + (1.0f - ALPHA_);
                    }
                }
                if (key >= NN_) v = -1e30f;
                s[jj][qi] = v;
            }
        }

        float mx0 = -1e30f, mx1 = -1e30f;
#pragma unroll
        for (int jj = 0; jj < 16; jj++) {
            mx0 = fmaxf(mx0, fmaxf(s[jj][0], s[jj][1]));
            mx1 = fmaxf(mx1, fmaxf(s[jj][2], s[jj][3]));
        }
        mx0 = fmaxf(mx0, __shfl_xor_sync(~0u, mx0, 1)); mx0 = fmaxf(mx0, __shfl_xor_sync(~0u, mx0, 2));
        mx1 = fmaxf(mx1, __shfl_xor_sync(~0u, mx1, 1)); mx1 = fmaxf(mx1, __shfl_xor_sync(~0u, mx1, 2));
        float mn0 = fmaxf(m0, mx0), mn1 = fmaxf(m1, mx1);
        float f0 = __expf(m0 - mn0), f1 = __expf(m1 - mn1);
        m0 = mn0; m1 = mn1;
        float rs0 = 0.f, rs1 = 0.f;
#pragma unroll
        for (int jj = 0; jj < 16; jj++) {
            float p0 = __expf(s[jj][0] - m0), p1 = __expf(s[jj][1] - m0);
            float p2 = __expf(s[jj][2] - m1), p3 = __expf(s[jj][3] - m1);
            s[jj][0] = p0; s[jj][1] = p1; s[jj][2] = p2; s[jj][3] = p3;
            rs0 += p0 + p1; rs1 += p2 + p3;
        }
        rs0 += __shfl_xor_sync(~0u, rs0, 1); rs0 += __shfl_xor_sync(~0u, rs0, 2);
        rs1 += __shfl_xor_sync(~0u, rs1, 1); rs1 += __shfl_xor_sync(~0u, rs1, 2);
        l0 = l0*f0 + rs0; l1 = l1*f1 + rs1;
#pragma unroll
        for (int j = 0; j < 8; j++) {
            o[j][0] *= f0; o[j][1] *= f0; o[j][2] *= f1; o[j][3] *= f1;
        }

#pragma unroll
        for (int kg = 0; kg < 8; kg++) {
            uint32_t ah[4], al[4];
            {
                float v00 = s[2*kg][0],   v01 = s[2*kg][1],   v02 = s[2*kg][2],   v03 = s[2*kg][3];
                float v10 = s[2*kg+1][0], v11 = s[2*kg+1][1], v12 = s[2*kg+1][2], v13 = s[2*kg+1][3];
                ah[0] = pack_bf2(v00, v01); ah[1] = pack_bf2(v02, v03);
                ah[2] = pack_bf2(v10, v11); ah[3] = pack_bf2(v12, v13);
                al[0] = pack_bf2(v00 - bf_hi(v00), v01 - bf_hi(v01));
                al[1] = pack_bf2(v02 - bf_hi(v02), v03 - bf_hi(v03));
                al[2] = pack_bf2(v10 - bf_hi(v10), v11 - bf_hi(v11));
                al[3] = pack_bf2(v12 - bf_hi(v12), v13 - bf_hi(v13));
            }
#pragma unroll
            for (int jp = 0; jp < 4; jp++) {
                uint32_t vh[4], vl[4];
                uint32_t vo = vb + (kg*16 + lrow)*QSTR + jp*32 + lsel*16;
                LDSM4T(vh, vo);
                LDSM4T(vl, vo + QHALF);
                MMA16816(o[2*jp],   ah[0],ah[1],ah[2],ah[3], vh[0], vh[1]);
                MMA16816(o[2*jp+1], ah[0],ah[1],ah[2],ah[3], vh[2], vh[3]);
                MMA16816(o[2*jp],   ah[0],ah[1],ah[2],ah[3], vl[0], vl[1]);
                MMA16816(o[2*jp+1], ah[0],ah[1],ah[2],ah[3], vl[2], vl[3]);
                MMA16816(o[2*jp],   al[0],al[1],al[2],al[3], vh[0], vh[1]);
                MMA16816(o[2*jp+1], al[0],al[1],al[2],al[3], vh[2], vh[3]);
            }
        }
        __syncthreads();
    }

    const float inv0 = 1.0f / l0, inv1 = 1.0f / l1;
    const int q0 = qt*128 + wid*16 + gq, q1 = q0 + 8;
#pragma unroll
    for (int j = 0; j < 8; j++) {
        int d0 = j*8 + tq*2;
        if (q0 < NN_) {
            long long off = (long long)(b*NN_ + q0)*CC + h*DD + d0;
            *reinterpret_cast<__half2*>(aoutF + off) = __floats2half2_rn(o[j][0]*inv0, o[j][1]*inv0);
        }
        if (q1 < NN_) {
            long long off = (long long)(b*NN_ + q1)*CC + h*DD + d0;
            *reinterpret_cast<__half2*>(aoutF + off) = __floats2half2_rn(o[j][2]*inv1, o[j][3]*inv1);
        }
    }
}

// ---------------- weight converters ----------------------------------------
__global__ void conv_pair(const float* __restrict__ src, u16* __restrict__ hi,
                          u16* __restrict__ lo, long long n4)
{
    long long i = (long long)blockIdx.x * blockDim.x + threadIdx.x;
    if (i >= n4) return;
    float4 v = reinterpret_cast<const float4*>(src)[i];
    u16 h0,l0,h1,l1,h2,l2,h3,l3;
    split_bf(v.x,h0,l0); split_bf(v.y,h1,l1); split_bf(v.z,h2,l2); split_bf(v.w,h3,l3);
    uint2 hp = { ((uint32_t)h1<<16)|h0, ((uint32_t)h3<<16)|h2 };
    uint2 lp = { ((uint32_t)l1<<16)|l0, ((uint32_t)l3<<16)|l2 };
    reinterpret_cast<uint2*>(hi)[i] = hp;
    reinterpret_cast<uint2*>(lo)[i] = lp;
}

__global__ void conv_half(const float* __restrict__ src, __half* __restrict__ dst, long long n4)
{
    long long i = (long long)blockIdx.x * blockDim.x + threadIdx.x;
    if (i >= n4) return;
    float4 v = reinterpret_cast<const float4*>(src)[i];
    __half2* d = reinterpret_cast<__half2*>(dst) + 2*i;
    d[0] = __floats2half2_rn(v.x, v.y);
    d[1] = __floats2half2_rn(v.z, v.w);
}

// ---------------- LayerNorm variants ---------------------------------------
__global__ void ln_kernel(const float* __restrict__ in,
                          const float* __restrict__ w, const float* __restrict__ b,
                          u16* __restrict__ outH, u16* __restrict__ outL)
{
    const long long row = blockIdx.x;
    const int tid = threadIdx.x;
    const float* rp = in + row * CC;
    float v0 = rp[tid], v1 = rp[tid+256], v2 = rp[tid+512];
    float s = v0+v1+v2, ss = v0*v0 + v1*v1 + v2*v2;
    const int wid = tid >> 5, lid = tid & 31;
    for (int o = 16; o; o >>= 1) { s += __shfl_xor_sync(~0u, s, o); ss += __shfl_xor_sync(~0u, ss, o); }
    __shared__ float rs[8], rq[8];
    if (lid == 0) { rs[wid] = s; rq[wid] = ss; }
    __syncthreads();
    float ts = 0.f, tq = 0.f;
#pragma unroll
    for (int i = 0; i < 8; i++) { ts += rs[i]; tq += rq[i]; }
    float mean = ts * (1.0f/CC);
    float rstd = rsqrtf(tq * (1.0f/CC) - mean*mean + EPS_);
#pragma unroll
    for (int k = 0; k < 3; k++) {
        int c = tid + k*256;
        float v = (k==0?v0:(k==1?v1:v2));
        float y = (v - mean)*rstd * w[c] + b[c];
        u16 h,l; split_bf(y,h,l);
        outH[row*CC + c] = h; outL[row*CC + c] = l;
    }
}

__global__ void ln_kernel_f(const float* __restrict__ in,
                            const float* __restrict__ w, const float* __restrict__ b,
                            __half* __restrict__ outF)
{
    const long long row = blockIdx.x;
    const int tid = threadIdx.x;
    const float* rp = in + row * CC;
    float v0 = rp[tid], v1 = rp[tid+256], v2 = rp[tid+512];
    float s = v0+v1+v2, ss = v0*v0 + v1*v1 + v2*v2;
    const int wid = tid >> 5, lid = tid & 31;
    for (int o = 16; o; o >>= 1) { s += __shfl_xor_sync(~0u, s, o); ss += __shfl_xor_sync(~0u, ss, o); }
    __shared__ float rs[8], rq[8];
    if (lid == 0) { rs[wid] = s; rq[wid] = ss; }
    __syncthreads();
    float ts = 0.f, tq = 0.f;
#pragma unroll
    for (int i = 0; i < 8; i++) { ts += rs[i]; tq += rq[i]; }
    float mean = ts * (1.0f/CC);
    float rstd = rsqrtf(tq * (1.0f/CC) - mean*mean + EPS_);
#pragma unroll
    for (int k = 0; k < 3; k++) {
        int c = tid + k*256;
        float v = (k==0?v0:(k==1?v1:v2));
        outF[row*CC + c] = __float2half_rn((v - mean)*rstd * w[c] + b[c]);
    }
}

// ---------------------------------------------------------------------------
extern "C" void kernel_launch(void* const* d_in, const int* in_sizes, int n_in,
                              void* d_out, int out_size)
{
    const float* x      = (const float*)d_in[0];
    const float* attn_w = (const float*)d_in[1];
    const float* ln1_w  = (const float*)d_in[2];
    const float* ln1_b  = (const float*)d_in[3];
    const float* qkv_w  = (const float*)d_in[4];
    const float* qkv_b  = (const float*)d_in[5];
    const float* proj_w = (const float*)d_in[6];
    const float* proj_b = (const float*)d_in[7];
    const float* ln2_w  = (const float*)d_in[8];
    const float* ln2_b  = (const float*)d_in[9];
    const float* fc1_w  = (const float*)d_in[10];
    const float* fc1_b  = (const float*)d_in[11];
    const float* fc2_w  = (const float*)d_in[12];
    const float* fc2_b  = (const float*)d_in[13];

    float* out_x     = (float*)d_out;
    float* out_patch = out_x + (long long)ROWS*CC;

    u16 *hlnH,*hlnL,*qkvwH,*qkvwL,*qkvH,*qkvL;
    __half *projwF,*fc1wF,*fc2wF,*aoutF,*h2F,*fc1F;
    float *x1;
    cudaGetSymbolAddress((void**)&hlnH, g_hlnH);   cudaGetSymbolAddress((void**)&hlnL, g_hlnL);
    cudaGetSymbolAddress((void**)&qkvwH, g_qkvwH); cudaGetSymbolAddress((void**)&qkvwL, g_qkvwL);
    cudaGetSymbolAddress((void**)&projwF, g_projwF);
    cudaGetSymbolAddress((void**)&fc1wF, g_fc1wF);
    cudaGetSymbolAddress((void**)&fc2wF, g_fc2wF);
    cudaGetSymbolAddress((void**)&qkvH, g_qkvH);   cudaGetSymbolAddress((void**)&qkvL, g_qkvL);
    cudaGetSymbolAddress((void**)&aoutF, g_aoutF);
    cudaGetSymbolAddress((void**)&x1, g_x1);
    cudaGetSymbolAddress((void**)&h2F, g_h2F);
    cudaGetSymbolAddress((void**)&fc1F, g_fc1F);

    const int SMEM128 = 2 * (2*128*80 + 2*128*80);   // 81920 (bf pair, qkv)
    const int SMEMHF  = 2 * (128*80 + 128*80);       // 40960 (fp16 single)
    cudaFuncSetAttribute(gemm_bf<128,0,1>, cudaFuncAttributeMaxDynamicSharedMemorySize, SMEM128);
    cudaFuncSetAttribute(gemm_hf<128,1,1>, cudaFuncAttributeMaxDynamicSharedMemorySize, SMEMHF);
    cudaFuncSetAttribute(gemm_hf<128,2,0>, cudaFuncAttributeMaxDynamicSharedMemorySize, SMEMHF);
    cudaFuncSetAttribute(flash_attn, cudaFuncAttributeMaxDynamicSharedMemorySize, FLASH_SMEM);

    // 0) weight conversions
    conv_pair<<<(int)(((long long)3*CC*CC/4 + 255)/256), 256>>>(qkv_w, qkvwH, qkvwL, (long long)3*CC*CC/4);
    conv_half<<<(int)(((long long)CC*CC/4   + 255)/256), 256>>>(proj_w, projwF, (long long)CC*CC/4);
    conv_half<<<(int)(((long long)HID_*CC/4 + 255)/256), 256>>>(fc1_w,  fc1wF,  (long long)HID_*CC/4);
    conv_half<<<(int)(((long long)CC*HID_/4 + 255)/256), 256>>>(fc2_w,  fc2wF,  (long long)CC*HID_/4);

    // 1) LN1 -> bf16 pair
    ln_kernel<<<ROWS, 256>>>(x, ln1_w, ln1_b, hlnH, hlnL);

    // 2) qkv GEMM (bf16x3) -> bf16 pair
    gemm_bf<128,0,1><<<dim3(3*CC/128, (ROWS+127)/128, 1), 256, SMEM128>>>(
        hlnH, hlnL, qkvwH, qkvwL, nullptr, qkvH, qkvL,
        ROWS, 3*CC, CC, CC, CC, 3*CC, qkv_b, nullptr, 0, 1.0f);

    // 3) fused flash attention (bf16x3) -> fp16 aout
    flash_attn<<<dim3(5, BB*HH_), 256, FLASH_SMEM>>>(
        qkvH, qkvL, attn_w, aoutF, out_patch);

    // 4) x1 = x + aout @ proj_w^T + proj_b   (fp16 single-pass)
    gemm_hf<128,2,0><<<dim3(CC/128, (ROWS+127)/128, 1), 256, SMEMHF>>>(
        aoutF, projwF, x1, nullptr,
        ROWS, CC, CC, CC, CC, CC, proj_b, x, CC);

    // 5) LN2 -> fp16
    ln_kernel_f<<<ROWS, 256>>>(x1, ln2_w, ln2_b, h2F);

    // 6) fc1 = gelu(h2 @ fc1_w^T + fc1_b) -> fp16  (single-pass)
    gemm_hf<128,1,1><<<dim3(HID_/128, (ROWS+127)/128, 1), 256, SMEMHF>>>(
        h2F, fc1wF, nullptr, fc1F,
        ROWS, HID_, CC, CC, CC, HID_, fc1_b, nullptr, 0);

    // 7) out = x1 + fc1 @ fc2_w^T + fc2_b  (single-pass)
    gemm_hf<128,2,0><<<dim3(CC/128, (ROWS+127)/128, 1), 256, SMEMHF>>>(
        fc1F, fc2wF, out_x, nullptr,
        ROWS, CC, HID_, HID_, HID_, CC, fc2_b, x1, CC);
}

// round 12
// speedup vs baseline: 2.4957x; 1.4052x over previous
#include <cuda_runtime.h>
#include <cuda_fp16.h>
#include <math.h>
#include <stdint.h>

// Problem constants
#define BB   32
#define NN_  577
#define CC   768
#define HH_  12
#define DD   64
#define HID_ 3072
#define ROWS (BB*NN_)                    // 18464
#define ALPHA_ 0.1f
#define EPS_ 1e-6f
#define SCALE_ 0.125f

// ---------------- scratch --------------------------------------------------
__device__ __half g_hlnF[(long long)ROWS*CC];
__device__ __half g_qkvwF[(long long)3*CC*CC];
__device__ __half g_projwF[(long long)CC*CC];
__device__ __half g_fc1wF[(long long)HID_*CC];
__device__ __half g_fc2wF[(long long)CC*HID_];
__device__ __half g_qkvF[(long long)ROWS*3*CC];
__device__ __half g_aoutF[(long long)ROWS*CC];
__device__ float g_x1[(long long)ROWS*CC];
__device__ __half g_h2F[(long long)ROWS*CC];
__device__ __half g_fc1F[(long long)ROWS*HID_];

// =================== asm helpers ===========================================
#define MMAH16816(d, a0,a1,a2,a3, b0,b1) \
    asm volatile("mma.sync.aligned.m16n8k16.row.col.f32.f16.f16.f32 " \
        "{%0,%1,%2,%3}, {%4,%5,%6,%7}, {%8,%9}, {%0,%1,%2,%3};" \
        : "+f"((d)[0]), "+f"((d)[1]), "+f"((d)[2]), "+f"((d)[3]) \
        : "r"(a0), "r"(a1), "r"(a2), "r"(a3), "r"(b0), "r"(b1))

#define LDSM4(r, ad) \
    asm volatile("ldmatrix.sync.aligned.m8n8.x4.shared.b16 {%0,%1,%2,%3}, [%4];" \
        : "=r"((r)[0]), "=r"((r)[1]), "=r"((r)[2]), "=r"((r)[3]) : "r"(ad))

#define LDSM4T(r, ad) \
    asm volatile("ldmatrix.sync.aligned.m8n8.x4.trans.shared.b16 {%0,%1,%2,%3}, [%4];" \
        : "=r"((r)[0]), "=r"((r)[1]), "=r"((r)[2]), "=r"((r)[3]) : "r"(ad))

__device__ __forceinline__ void cpa16(uint32_t dst, const void* src, int sz) {
    asm volatile("cp.async.cg.shared.global [%0], [%1], 16, %2;" :: "r"(dst), "l"(src), "r"(sz) : "memory");
}
#define CP_COMMIT() asm volatile("cp.async.commit_group;" ::: "memory")
#define CP_WAIT1()  asm volatile("cp.async.wait_group 1;" ::: "memory")
#define CP_WAIT0()  asm volatile("cp.async.wait_group 0;" ::: "memory")

__device__ __forceinline__ uint32_t smem_u32(const void* p) {
    uint32_t a;
    asm("{ .reg .u64 t; cvta.to.shared.u64 t, %1; cvt.u32.u64 %0, t; }" : "=r"(a) : "l"(p));
    return a;
}
__device__ __forceinline__ uint32_t pack_hf2(float x, float y) {
    __half2 h = __floats2half2_rn(x, y);
    return *reinterpret_cast<uint32_t*>(&h);
}

// =================== single-pass fp16 HMMA GEMM ============================
// C = epi(A @ B^T + bias); A [M,K] fp16 ldA, B [N,K] fp16 ldB.
// EPI: 0 none, 1 exact GELU, 2 +Res.  OUTF: 0 fp32 C, 1 fp16 CF.
template<int BN, int EPI, int OUTF>
__global__ void __launch_bounds__(256, 2)
gemm_hf(const __half* __restrict__ A, const __half* __restrict__ B,
        float* __restrict__ C, __half* __restrict__ CF,
        int M, int N, int K, int ldA, int ldB, int ldC,
        const float* __restrict__ bias,
        const float* __restrict__ Res, int ldRes)
{
    constexpr int ABYTES = 128 * 80;
    constexpr int BBYTES = BN * 80;
    constexpr int STAGE  = ABYTES + BBYTES;      // 20480 for BN=128
    constexpr int NT     = BN / 16;
    constexpr int BCH    = BN / 64;

    const int tid = threadIdx.x, lane = tid & 31, wid = tid >> 5;
    const int gq = lane >> 2, tq = lane & 3;
    const int warp_m = wid & 3, warp_n = wid >> 2;

    const int rowBase = blockIdx.y * 128;
    const int colBase = blockIdx.x * BN;

    extern __shared__ char smraw[];
    const uint32_t smb = smem_u32(smraw);

    float acc[2][NT][4];
#pragma unroll
    for (int i = 0; i < 2; i++)
#pragma unroll
        for (int j = 0; j < NT; j++)
#pragma unroll
            for (int q = 0; q < 4; q++) acc[i][j][q] = 0.f;

    const int nst = K / 32;

    auto load_stage = [&](int s) {
        const int k0 = s * 32;
        const uint32_t base = smb + (s & 1) * STAGE;
#pragma unroll
        for (int i = 0; i < 2; i++) {
            int cid = tid + i*256;
            int row = cid >> 2, q = cid & 3;
            int gr = rowBase + row;
            int sz = (gr < M) ? 16 : 0;
            long long go = (long long)(gr < M ? gr : 0) * ldA + k0 + q*8;
            cpa16(base + row*80 + q*16, A + go, sz);
        }
#pragma unroll
        for (int i = 0; i < BCH; i++) {
            int cid = tid + i*256;
            int row = cid >> 2, q = cid & 3;
            int gn = colBase + row;
            int sz = (gn < N) ? 16 : 0;
            long long go = (long long)(gn < N ? gn : 0) * ldB + k0 + q*8;
            cpa16(base + ABYTES + row*80 + q*16, B + go, sz);
        }
    };

    const uint32_t lrow = lane & 15, lsel = lane >> 4;
    const uint32_t aOff = (warp_m*32 + lrow)*80 + lsel*16;
    const uint32_t bOff = (warp_n*(BN/2) + lrow)*80 + lsel*16;

    load_stage(0);
    CP_COMMIT();

    for (int s = 0; s < nst; s++) {
        if (s + 1 < nst) { load_stage(s + 1); CP_COMMIT(); CP_WAIT1(); }
        else             { CP_WAIT0(); }
        __syncthreads();

        const uint32_t st = smb + (s & 1) * STAGE;
#pragma unroll
        for (int ks = 0; ks < 2; ks++) {
            uint32_t a[2][4];
#pragma unroll
            for (int i = 0; i < 2; i++)
                LDSM4(a[i], st + aOff + i*1280 + ks*32);
#pragma unroll
            for (int j2 = 0; j2 < NT/2; j2++) {
                uint32_t bf[4];
                LDSM4(bf, st + ABYTES + bOff + j2*1280 + ks*32);
#pragma unroll
                for (int i = 0; i < 2; i++) {
                    MMAH16816(acc[i][2*j2],   a[i][0],a[i][1],a[i][2],a[i][3], bf[0], bf[2]);
                    MMAH16816(acc[i][2*j2+1], a[i][0],a[i][1],a[i][2],a[i][3], bf[1], bf[3]);
                }
            }
        }
        __syncthreads();
    }

#pragma unroll
    for (int i = 0; i < 2; i++) {
#pragma unroll
        for (int half = 0; half < 2; half++) {
            const int r = rowBase + warp_m*32 + i*16 + gq + half*8;
            if (r >= M) continue;
#pragma unroll
            for (int j = 0; j < NT; j++) {
                const int c0 = colBase + warp_n*(BN/2) + j*8 + tq*2;
                float v0 = acc[i][j][half*2 + 0];
                float v1 = acc[i][j][half*2 + 1];
                if (bias) { v0 += bias[c0]; v1 += (c0+1 < N) ? bias[c0+1] : 0.f; }
                if (EPI == 1) {
                    v0 = 0.5f*v0*(1.0f + erff(v0*0.70710678118654752f));
                    v1 = 0.5f*v1*(1.0f + erff(v1*0.70710678118654752f));
                } else if (EPI == 2) {
                    v0 += Res[(long long)r*ldRes + c0];
                    if (c0+1 < N) v1 += Res[(long long)r*ldRes + c0 + 1];
                }
                if (OUTF) {
                    if (c0 + 1 < N) {
                        *reinterpret_cast<__half2*>(CF + (long long)r*ldC + c0) = __floats2half2_rn(v0, v1);
                    } else if (c0 < N) {
                        CF[(long long)r*ldC + c0] = __float2half_rn(v0);
                    }
                } else {
                    if (c0 < N)     C[(long long)r*ldC + c0]     = v0;
                    if (c0+1 < N)   C[(long long)r*ldC + c0 + 1] = v1;
                }
            }
        }
    }
}

// =================== fused flash attention (fp16 single-pass) ==============
#define QSTR 144
#define QB   18432             // 128*144 bytes per tile
#define KBASE QB               // K stages at 18432
#define VBASE (QB + 2*QB)      // 55296
#define FLASH_SMEM (VBASE + 2*QB)   // 92160

__global__ void __launch_bounds__(256, 1)
flash_attn(const __half* __restrict__ qkvF,
           const float* __restrict__ attn_w,
           __half* __restrict__ aoutF,
           float* __restrict__ patch_out)
{
    const int z = blockIdx.y, qt = blockIdx.x;
    const int b = z / HH_, h = z % HH_;
    const int tid = threadIdx.x, lane = tid & 31, wid = tid >> 5;
    const int gq = lane >> 2, tq = lane & 3;

    extern __shared__ char smraw[];
    const uint32_t smb = smem_u32(smraw);

    // ---- load Q tile (once) ----
#pragma unroll
    for (int i = 0; i < 4; i++) {
        int cid = tid + i*256;
        int row = cid >> 3, ch = cid & 7;
        int gr = qt*128 + row;
        int sz = (gr < NN_) ? 16 : 0;
        long long go = (long long)(b*NN_ + (gr < NN_ ? gr : 0))*(3*CC) + h*DD + ch*8;
        cpa16(smb + row*QSTR + ch*16, qkvF + go, sz);
    }
    auto load_kv = [&](int t) {
        const uint32_t kb = smb + KBASE + (t & 1)*QB;
        const uint32_t vb = smb + VBASE + (t & 1)*QB;
#pragma unroll
        for (int i = 0; i < 4; i++) {
            int cid = tid + i*256;
            int row = cid >> 3, ch = cid & 7;
            int gk = t*128 + row;
            int sz = (gk < NN_) ? 16 : 0;
            long long base = (long long)(b*NN_ + (gk < NN_ ? gk : 0))*(3*CC) + h*DD + ch*8;
            cpa16(kb + row*QSTR + ch*16, qkvF + base + CC,   sz);
            cpa16(vb + row*QSTR + ch*16, qkvF + base + 2*CC, sz);
        }
    };

    float o[8][4];
#pragma unroll
    for (int j = 0; j < 8; j++)
#pragma unroll
        for (int q = 0; q < 4; q++) o[j][q] = 0.f;
    float m0 = -INFINITY, m1 = -INFINITY, l0 = 0.f, l1 = 0.f;

    const uint32_t lrow = lane & 15, lsel = lane >> 4;
    const uint32_t qOff = (wid*16 + lrow)*QSTR + lsel*16;
    const bool clsrow = (qt == 0) && (wid == 0) && (gq == 0);

    load_kv(0);
    CP_COMMIT();

    for (int t = 0; t < 5; t++) {
        if (t < 4) { load_kv(t + 1); CP_COMMIT(); CP_WAIT1(); }
        else       { CP_WAIT0(); }
        __syncthreads();

        const uint32_t kb = smb + KBASE + (t & 1)*QB;
        const uint32_t vb = smb + VBASE + (t & 1)*QB;

        // ---- S = Q @ K^T (single fp16 pass) ----
        float s[16][4];
#pragma unroll
        for (int j = 0; j < 16; j++)
#pragma unroll
            for (int q = 0; q < 4; q++) s[j][q] = 0.f;

#pragma unroll
        for (int kg = 0; kg < 4; kg++) {
            uint32_t qh[4];
            LDSM4(qh, smb + qOff + kg*32);
#pragma unroll
            for (int jj = 0; jj < 8; jj++) {
                uint32_t kh[4];
                LDSM4(kh, kb + (jj*16 + lrow)*QSTR + lsel*16 + kg*32);
                MMAH16816(s[2*jj],   qh[0],qh[1],qh[2],qh[3], kh[0], kh[2]);
                MMAH16816(s[2*jj+1], qh[0],qh[1],qh[2],qh[3], kh[1], kh[3]);
            }
        }

        // ---- scale + CLS factor + patch + mask ----
#pragma unroll
        for (int jj = 0; jj < 16; jj++) {
#pragma unroll
            for (int qi = 0; qi < 4; qi++) {
                float v = s[jj][qi] * SCALE_;
                int key = t*128 + jj*8 + tq*2 + (qi & 1);
                if (clsrow && qi < 2) {
                    if (key >= 1 && key < NN_) {
                        patch_out[(long long)z*(NN_-1) + key - 1] = v;
                        v *= attn_w[(long long)b*(NN_-1) + key - 1] * ALPHA_ + (1.0f - ALPHA_);
                    }
                }
                if (key >= NN_) v = -1e30f;
                s[jj][qi] = v;
            }
        }

        // ---- online softmax ----
        float mx0 = -1e30f, mx1 = -1e30f;
#pragma unroll
        for (int jj = 0; jj < 16; jj++) {
            mx0 = fmaxf(mx0, fmaxf(s[jj][0], s[jj][1]));
            mx1 = fmaxf(mx1, fmaxf(s[jj][2], s[jj][3]));
        }
        mx0 = fmaxf(mx0, __shfl_xor_sync(~0u, mx0, 1)); mx0 = fmaxf(mx0, __shfl_xor_sync(~0u, mx0, 2));
        mx1 = fmaxf(mx1, __shfl_xor_sync(~0u, mx1, 1)); mx1 = fmaxf(mx1, __shfl_xor_sync(~0u, mx1, 2));
        float mn0 = fmaxf(m0, mx0), mn1 = fmaxf(m1, mx1);
        float f0 = __expf(m0 - mn0), f1 = __expf(m1 - mn1);
        m0 = mn0; m1 = mn1;
        float rs0 = 0.f, rs1 = 0.f;
#pragma unroll
        for (int jj = 0; jj < 16; jj++) {
            float p0 = __expf(s[jj][0] - m0), p1 = __expf(s[jj][1] - m0);
            float p2 = __expf(s[jj][2] - m1), p3 = __expf(s[jj][3] - m1);
            s[jj][0] = p0; s[jj][1] = p1; s[jj][2] = p2; s[jj][3] = p3;
            rs0 += p0 + p1; rs1 += p2 + p3;
        }
        rs0 += __shfl_xor_sync(~0u, rs0, 1); rs0 += __shfl_xor_sync(~0u, rs0, 2);
        rs1 += __shfl_xor_sync(~0u, rs1, 1); rs1 += __shfl_xor_sync(~0u, rs1, 2);
        l0 = l0*f0 + rs0; l1 = l1*f1 + rs1;
#pragma unroll
        for (int j = 0; j < 8; j++) {
            o[j][0] *= f0; o[j][1] *= f0; o[j][2] *= f1; o[j][3] *= f1;
        }

        // ---- O += P @ V (single fp16 pass; V key-major, trans ldmatrix) ----
#pragma unroll
        for (int kg = 0; kg < 8; kg++) {
            uint32_t ah[4];
            ah[0] = pack_hf2(s[2*kg][0],   s[2*kg][1]);
            ah[1] = pack_hf2(s[2*kg][2],   s[2*kg][3]);
            ah[2] = pack_hf2(s[2*kg+1][0], s[2*kg+1][1]);
            ah[3] = pack_hf2(s[2*kg+1][2], s[2*kg+1][3]);
#pragma unroll
            for (int jp = 0; jp < 4; jp++) {
                uint32_t vh[4];
                LDSM4T(vh, vb + (kg*16 + lrow)*QSTR + jp*32 + lsel*16);
                MMAH16816(o[2*jp],   ah[0],ah[1],ah[2],ah[3], vh[0], vh[1]);
                MMAH16816(o[2*jp+1], ah[0],ah[1],ah[2],ah[3], vh[2], vh[3]);
            }
        }
        __syncthreads();
    }

    // ---- epilogue ----
    const float inv0 = 1.0f / l0, inv1 = 1.0f / l1;
    const int q0 = qt*128 + wid*16 + gq, q1 = q0 + 8;
#pragma unroll
    for (int j = 0; j < 8; j++) {
        int d0 = j*8 + tq*2;
        if (q0 < NN_) {
            long long off = (long long)(b*NN_ + q0)*CC + h*DD + d0;
            *reinterpret_cast<__half2*>(aoutF + off) = __floats2half2_rn(o[j][0]*inv0, o[j][1]*inv0);
        }
        if (q1 < NN_) {
            long long off = (long long)(b*NN_ + q1)*CC + h*DD + d0;
            *reinterpret_cast<__half2*>(aoutF + off) = __floats2half2_rn(o[j][2]*inv1, o[j][3]*inv1);
        }
    }
}

// ---------------- weight fp32 -> fp16 --------------------------------------
__global__ void conv_half(const float* __restrict__ src, __half* __restrict__ dst, long long n4)
{
    long long i = (long long)blockIdx.x * blockDim.x + threadIdx.x;
    if (i >= n4) return;
    float4 v = reinterpret_cast<const float4*>(src)[i];
    __half2* d = reinterpret_cast<__half2*>(dst) + 2*i;
    d[0] = __floats2half2_rn(v.x, v.y);
    d[1] = __floats2half2_rn(v.z, v.w);
}

// ---------------- LayerNorm -> fp16 ----------------------------------------
__global__ void ln_kernel_f(const float* __restrict__ in,
                            const float* __restrict__ w, const float* __restrict__ b,
                            __half* __restrict__ outF)
{
    const long long row = blockIdx.x;
    const int tid = threadIdx.x;
    const float* rp = in + row * CC;
    float v0 = rp[tid], v1 = rp[tid+256], v2 = rp[tid+512];
    float s = v0+v1+v2, ss = v0*v0 + v1*v1 + v2*v2;
    const int wid = tid >> 5, lid = tid & 31;
    for (int o = 16; o; o >>= 1) { s += __shfl_xor_sync(~0u, s, o); ss += __shfl_xor_sync(~0u, ss, o); }
    __shared__ float rs[8], rq[8];
    if (lid == 0) { rs[wid] = s; rq[wid] = ss; }
    __syncthreads();
    float ts = 0.f, tq = 0.f;
#pragma unroll
    for (int i = 0; i < 8; i++) { ts += rs[i]; tq += rq[i]; }
    float mean = ts * (1.0f/CC);
    float rstd = rsqrtf(tq * (1.0f/CC) - mean*mean + EPS_);
#pragma unroll
    for (int k = 0; k < 3; k++) {
        int c = tid + k*256;
        float v = (k==0?v0:(k==1?v1:v2));
        outF[row*CC + c] = __float2half_rn((v - mean)*rstd * w[c] + b[c]);
    }
}

// ---------------------------------------------------------------------------
extern "C" void kernel_launch(void* const* d_in, const int* in_sizes, int n_in,
                              void* d_out, int out_size)
{
    const float* x      = (const float*)d_in[0];
    const float* attn_w = (const float*)d_in[1];
    const float* ln1_w  = (const float*)d_in[2];
    const float* ln1_b  = (const float*)d_in[3];
    const float* qkv_w  = (const float*)d_in[4];
    const float* qkv_b  = (const float*)d_in[5];
    const float* proj_w = (const float*)d_in[6];
    const float* proj_b = (const float*)d_in[7];
    const float* ln2_w  = (const float*)d_in[8];
    const float* ln2_b  = (const float*)d_in[9];
    const float* fc1_w  = (const float*)d_in[10];
    const float* fc1_b  = (const float*)d_in[11];
    const float* fc2_w  = (const float*)d_in[12];
    const float* fc2_b  = (const float*)d_in[13];

    float* out_x     = (float*)d_out;
    float* out_patch = out_x + (long long)ROWS*CC;

    __half *hlnF,*qkvwF,*projwF,*fc1wF,*fc2wF,*qkvF,*aoutF,*h2F,*fc1F;
    float *x1;
    cudaGetSymbolAddress((void**)&hlnF, g_hlnF);
    cudaGetSymbolAddress((void**)&qkvwF, g_qkvwF);
    cudaGetSymbolAddress((void**)&projwF, g_projwF);
    cudaGetSymbolAddress((void**)&fc1wF, g_fc1wF);
    cudaGetSymbolAddress((void**)&fc2wF, g_fc2wF);
    cudaGetSymbolAddress((void**)&qkvF, g_qkvF);
    cudaGetSymbolAddress((void**)&aoutF, g_aoutF);
    cudaGetSymbolAddress((void**)&x1, g_x1);
    cudaGetSymbolAddress((void**)&h2F, g_h2F);
    cudaGetSymbolAddress((void**)&fc1F, g_fc1F);

    const int SMEMHF = 2 * (128*80 + 128*80);       // 40960
    cudaFuncSetAttribute(gemm_hf<128,0,1>, cudaFuncAttributeMaxDynamicSharedMemorySize, SMEMHF);
    cudaFuncSetAttribute(gemm_hf<128,1,1>, cudaFuncAttributeMaxDynamicSharedMemorySize, SMEMHF);
    cudaFuncSetAttribute(gemm_hf<128,2,0>, cudaFuncAttributeMaxDynamicSharedMemorySize, SMEMHF);
    cudaFuncSetAttribute(flash_attn, cudaFuncAttributeMaxDynamicSharedMemorySize, FLASH_SMEM);

    // 0) weight conversions
    conv_half<<<(int)(((long long)3*CC*CC/4 + 255)/256), 256>>>(qkv_w,  qkvwF, (long long)3*CC*CC/4);
    conv_half<<<(int)(((long long)CC*CC/4   + 255)/256), 256>>>(proj_w, projwF, (long long)CC*CC/4);
    conv_half<<<(int)(((long long)HID_*CC/4 + 255)/256), 256>>>(fc1_w,  fc1wF,  (long long)HID_*CC/4);
    conv_half<<<(int)(((long long)CC*HID_/4 + 255)/256), 256>>>(fc2_w,  fc2wF,  (long long)CC*HID_/4);

    // 1) LN1 -> fp16
    ln_kernel_f<<<ROWS, 256>>>(x, ln1_w, ln1_b, hlnF);

    // 2) qkv = hln @ qkv_w^T + qkv_b -> fp16
    gemm_hf<128,0,1><<<dim3(3*CC/128, (ROWS+127)/128, 1), 256, SMEMHF>>>(
        hlnF, qkvwF, nullptr, qkvF,
        ROWS, 3*CC, CC, CC, CC, 3*CC, qkv_b, nullptr, 0);

    // 3) fused flash attention -> fp16 aout + patch_attn
    flash_attn<<<dim3(5, BB*HH_), 256, FLASH_SMEM>>>(
        qkvF, attn_w, aoutF, out_patch);

    // 4) x1 = x + aout @ proj_w^T + proj_b
    gemm_hf<128,2,0><<<dim3(CC/128, (ROWS+127)/128, 1), 256, SMEMHF>>>(
        aoutF, projwF, x1, nullptr,
        ROWS, CC, CC, CC, CC, CC, proj_b, x, CC);

    // 5) LN2 -> fp16
    ln_kernel_f<<<ROWS, 256>>>(x1, ln2_w, ln2_b, h2F);

    // 6) fc1 = gelu(h2 @ fc1_w^T + fc1_b) -> fp16
    gemm_hf<128,1,1><<<dim3(HID_/128, (ROWS+127)/128, 1), 256, SMEMHF>>>(
        h2F, fc1wF, nullptr, fc1F,
        ROWS, HID_, CC, CC, CC, HID_, fc1_b, nullptr, 0);

    // 7) out = x1 + fc1 @ fc2_w^T + fc2_b
    gemm_hf<128,2,0><<<dim3(CC/128, (ROWS+127)/128, 1), 256, SMEMHF>>>(
        fc1F, fc2wF, out_x, nullptr,
        ROWS, CC, HID_, HID_, HID_, CC, fc2_b, x1, CC);
}

// round 14
// speedup vs baseline: 2.8041x; 1.1236x over previous
#include <cuda_runtime.h>
#include <cuda_fp16.h>
#include <math.h>
#include <stdint.h>

// Problem constants
#define BB   32
#define NN_  577
#define CC   768
#define HH_  12
#define DD   64
#define HID_ 3072
#define ROWS (BB*NN_)                    // 18464
#define ALPHA_ 0.1f
#define EPS_ 1e-6f
#define SCALE_ 0.125f

// ---------------- scratch --------------------------------------------------
__device__ __half g_hlnF[(long long)ROWS*CC];
__device__ __half g_qkvwF[(long long)3*CC*CC];
__device__ __half g_projwF[(long long)CC*CC];
__device__ __half g_fc1wF[(long long)HID_*CC];
__device__ __half g_fc2wF[(long long)CC*HID_];
__device__ __half g_qkvF[(long long)ROWS*3*CC];
__device__ __half g_aoutF[(long long)ROWS*CC];
__device__ float g_x1[(long long)ROWS*CC];
__device__ __half g_h2F[(long long)ROWS*CC];
__device__ __half g_fc1F[(long long)ROWS*HID_];

// =================== asm helpers ===========================================
#define MMAH16816(d, a0,a1,a2,a3, b0,b1) \
    asm volatile("mma.sync.aligned.m16n8k16.row.col.f32.f16.f16.f32 " \
        "{%0,%1,%2,%3}, {%4,%5,%6,%7}, {%8,%9}, {%0,%1,%2,%3};" \
        : "+f"((d)[0]), "+f"((d)[1]), "+f"((d)[2]), "+f"((d)[3]) \
        : "r"(a0), "r"(a1), "r"(a2), "r"(a3), "r"(b0), "r"(b1))

#define LDSM4(r, ad) \
    asm volatile("ldmatrix.sync.aligned.m8n8.x4.shared.b16 {%0,%1,%2,%3}, [%4];" \
        : "=r"((r)[0]), "=r"((r)[1]), "=r"((r)[2]), "=r"((r)[3]) : "r"(ad))

#define LDSM4T(r, ad) \
    asm volatile("ldmatrix.sync.aligned.m8n8.x4.trans.shared.b16 {%0,%1,%2,%3}, [%4];" \
        : "=r"((r)[0]), "=r"((r)[1]), "=r"((r)[2]), "=r"((r)[3]) : "r"(ad))

__device__ __forceinline__ void cpa16(uint32_t dst, const void* src, int sz) {
    asm volatile("cp.async.cg.shared.global [%0], [%1], 16, %2;" :: "r"(dst), "l"(src), "r"(sz) : "memory");
}
#define CP_COMMIT() asm volatile("cp.async.commit_group;" ::: "memory")
#define CP_WAIT1()  asm volatile("cp.async.wait_group 1;" ::: "memory")
#define CP_WAIT0()  asm volatile("cp.async.wait_group 0;" ::: "memory")

__device__ __forceinline__ uint32_t smem_u32(const void* p) {
    uint32_t a;
    asm("{ .reg .u64 t; cvta.to.shared.u64 t, %1; cvt.u32.u64 %0, t; }" : "=r"(a) : "l"(p));
    return a;
}
__device__ __forceinline__ uint32_t pack_hf2(float x, float y) {
    __half2 h = __floats2half2_rn(x, y);
    return *reinterpret_cast<uint32_t*>(&h);
}

// =================== single-pass fp16 HMMA GEMM (BK=64) ====================
// C = epi(A @ B^T + bias); A [M,K] fp16 ldA, B [N,K] fp16 ldB.
// BK=64 per stage, row stride 144 B (128 data + 16 pad; conflict-free ldmatrix).
// K % 64 == 0 required.
// EPI: 0 none, 1 exact GELU, 2 +Res.  OUTF: 0 fp32 C, 1 fp16 CF.
template<int BN, int EPI, int OUTF>
__global__ void __launch_bounds__(256, 2)
gemm_hf(const __half* __restrict__ A, const __half* __restrict__ B,
        float* __restrict__ C, __half* __restrict__ CF,
        int M, int N, int K, int ldA, int ldB, int ldC,
        const float* __restrict__ bias,
        const float* __restrict__ Res, int ldRes)
{
    constexpr int RSTR   = 144;                  // bytes per row in smem
    constexpr int ABYTES = 128 * RSTR;           // 18432
    constexpr int BBYTES = BN * RSTR;
    constexpr int STAGE  = ABYTES + BBYTES;      // 36864 for BN=128
    constexpr int NT     = BN / 16;
    constexpr int BPASS  = BN / 32;              // B cp.async passes (BN rows * 8 / 256)

    const int tid = threadIdx.x, lane = tid & 31, wid = tid >> 5;
    const int gq = lane >> 2, tq = lane & 3;
    const int warp_m = wid & 3, warp_n = wid >> 2;

    const int rowBase = blockIdx.y * 128;
    const int colBase = blockIdx.x * BN;

    extern __shared__ char smraw[];
    const uint32_t smb = smem_u32(smraw);

    float acc[2][NT][4];
#pragma unroll
    for (int i = 0; i < 2; i++)
#pragma unroll
        for (int j = 0; j < NT; j++)
#pragma unroll
            for (int q = 0; q < 4; q++) acc[i][j][q] = 0.f;

    const int nst = K / 64;

    auto load_stage = [&](int s) {
        const int k0 = s * 64;
        const uint32_t base = smb + (s & 1) * STAGE;
#pragma unroll
        for (int i = 0; i < 4; i++) {                  // A: 128 rows x 8 chunks
            int cid = tid + i*256;
            int row = cid >> 3, q = cid & 7;
            int gr = rowBase + row;
            int sz = (gr < M) ? 16 : 0;
            long long go = (long long)(gr < M ? gr : 0) * ldA + k0 + q*8;
            cpa16(base + row*RSTR + q*16, A + go, sz);
        }
#pragma unroll
        for (int i = 0; i < BPASS; i++) {              // B: BN rows x 8 chunks
            int cid = tid + i*256;
            int row = cid >> 3, q = cid & 7;
            int gn = colBase + row;
            int sz = (gn < N) ? 16 : 0;
            long long go = (long long)(gn < N ? gn : 0) * ldB + k0 + q*8;
            cpa16(base + ABYTES + row*RSTR + q*16, B + go, sz);
        }
    };

    const uint32_t lrow = lane & 15, lsel = lane >> 4;
    const uint32_t aOff = (warp_m*32 + lrow)*RSTR + lsel*16;
    const uint32_t bOff = (warp_n*(BN/2) + lrow)*RSTR + lsel*16;

    load_stage(0);
    CP_COMMIT();

    for (int s = 0; s < nst; s++) {
        if (s + 1 < nst) { load_stage(s + 1); CP_COMMIT(); CP_WAIT1(); }
        else             { CP_WAIT0(); }
        __syncthreads();

        const uint32_t st = smb + (s & 1) * STAGE;
#pragma unroll
        for (int ks = 0; ks < 4; ks++) {
            uint32_t a[2][4];
#pragma unroll
            for (int i = 0; i < 2; i++)
                LDSM4(a[i], st + aOff + i*16*RSTR + ks*32);
#pragma unroll
            for (int j2 = 0; j2 < NT/2; j2++) {
                uint32_t bf[4];
                LDSM4(bf, st + ABYTES + bOff + j2*16*RSTR + ks*32);
#pragma unroll
                for (int i = 0; i < 2; i++) {
                    MMAH16816(acc[i][2*j2],   a[i][0],a[i][1],a[i][2],a[i][3], bf[0], bf[2]);
                    MMAH16816(acc[i][2*j2+1], a[i][0],a[i][1],a[i][2],a[i][3], bf[1], bf[3]);
                }
            }
        }
        __syncthreads();
    }

#pragma unroll
    for (int i = 0; i < 2; i++) {
#pragma unroll
        for (int half = 0; half < 2; half++) {
            const int r = rowBase + warp_m*32 + i*16 + gq + half*8;
            if (r >= M) continue;
#pragma unroll
            for (int j = 0; j < NT; j++) {
                const int c0 = colBase + warp_n*(BN/2) + j*8 + tq*2;
                float v0 = acc[i][j][half*2 + 0];
                float v1 = acc[i][j][half*2 + 1];
                if (bias) { v0 += bias[c0]; v1 += (c0+1 < N) ? bias[c0+1] : 0.f; }
                if (EPI == 1) {
                    v0 = 0.5f*v0*(1.0f + erff(v0*0.70710678118654752f));
                    v1 = 0.5f*v1*(1.0f + erff(v1*0.70710678118654752f));
                } else if (EPI == 2) {
                    v0 += Res[(long long)r*ldRes + c0];
                    if (c0+1 < N) v1 += Res[(long long)r*ldRes + c0 + 1];
                }
                if (OUTF) {
                    if (c0 + 1 < N) {
                        *reinterpret_cast<__half2*>(CF + (long long)r*ldC + c0) = __floats2half2_rn(v0, v1);
                    } else if (c0 < N) {
                        CF[(long long)r*ldC + c0] = __float2half_rn(v0);
                    }
                } else {
                    if (c0 < N)     C[(long long)r*ldC + c0]     = v0;
                    if (c0+1 < N)   C[(long long)r*ldC + c0 + 1] = v1;
                }
            }
        }
    }
}

// =================== fused flash attention (fp16 single-pass) ==============
#define QSTR 144
#define QB   18432             // 128*144 bytes per tile
#define KBASE QB
#define VBASE (QB + 2*QB)      // 55296
#define FLASH_SMEM (VBASE + 2*QB)   // 92160

__global__ void __launch_bounds__(256, 1)
flash_attn(const __half* __restrict__ qkvF,
           const float* __restrict__ attn_w,
           __half* __restrict__ aoutF,
           float* __restrict__ patch_out)
{
    const int z = blockIdx.y, qt = blockIdx.x;
    const int b = z / HH_, h = z % HH_;
    const int tid = threadIdx.x, lane = tid & 31, wid = tid >> 5;
    const int gq = lane >> 2, tq = lane & 3;

    extern __shared__ char smraw[];
    const uint32_t smb = smem_u32(smraw);

#pragma unroll
    for (int i = 0; i < 4; i++) {
        int cid = tid + i*256;
        int row = cid >> 3, ch = cid & 7;
        int gr = qt*128 + row;
        int sz = (gr < NN_) ? 16 : 0;
        long long go = (long long)(b*NN_ + (gr < NN_ ? gr : 0))*(3*CC) + h*DD + ch*8;
        cpa16(smb + row*QSTR + ch*16, qkvF + go, sz);
    }
    auto load_kv = [&](int t) {
        const uint32_t kb = smb + KBASE + (t & 1)*QB;
        const uint32_t vb = smb + VBASE + (t & 1)*QB;
#pragma unroll
        for (int i = 0; i < 4; i++) {
            int cid = tid + i*256;
            int row = cid >> 3, ch = cid & 7;
            int gk = t*128 + row;
            int sz = (gk < NN_) ? 16 : 0;
            long long base = (long long)(b*NN_ + (gk < NN_ ? gk : 0))*(3*CC) + h*DD + ch*8;
            cpa16(kb + row*QSTR + ch*16, qkvF + base + CC,   sz);
            cpa16(vb + row*QSTR + ch*16, qkvF + base + 2*CC, sz);
        }
    };

    float o[8][4];
#pragma unroll
    for (int j = 0; j < 8; j++)
#pragma unroll
        for (int q = 0; q < 4; q++) o[j][q] = 0.f;
    float m0 = -INFINITY, m1 = -INFINITY, l0 = 0.f, l1 = 0.f;

    const uint32_t lrow = lane & 15, lsel = lane >> 4;
    const uint32_t qOff = (wid*16 + lrow)*QSTR + lsel*16;
    const bool clsrow = (qt == 0) && (wid == 0) && (gq == 0);

    load_kv(0);
    CP_COMMIT();

    for (int t = 0; t < 5; t++) {
        if (t < 4) { load_kv(t + 1); CP_COMMIT(); CP_WAIT1(); }
        else       { CP_WAIT0(); }
        __syncthreads();

        const uint32_t kb = smb + KBASE + (t & 1)*QB;
        const uint32_t vb = smb + VBASE + (t & 1)*QB;

        float s[16][4];
#pragma unroll
        for (int j = 0; j < 16; j++)
#pragma unroll
            for (int q = 0; q < 4; q++) s[j][q] = 0.f;

#pragma unroll
        for (int kg = 0; kg < 4; kg++) {
            uint32_t qh[4];
            LDSM4(qh, smb + qOff + kg*32);
#pragma unroll
            for (int jj = 0; jj < 8; jj++) {
                uint32_t kh[4];
                LDSM4(kh, kb + (jj*16 + lrow)*QSTR + lsel*16 + kg*32);
                MMAH16816(s[2*jj],   qh[0],qh[1],qh[2],qh[3], kh[0], kh[2]);
                MMAH16816(s[2*jj+1], qh[0],qh[1],qh[2],qh[3], kh[1], kh[3]);
            }
        }

#pragma unroll
        for (int jj = 0; jj < 16; jj++) {
#pragma unroll
            for (int qi = 0; qi < 4; qi++) {
                float v = s[jj][qi] * SCALE_;
                int key = t*128 + jj*8 + tq*2 + (qi & 1);
                if (clsrow && qi < 2) {
                    if (key >= 1 && key < NN_) {
                        patch_out[(long long)z*(NN_-1) + key - 1] = v;
                        v *= attn_w[(long long)b*(NN_-1) + key - 1] * ALPHA_ + (1.0f - ALPHA_);
                    }
                }
                if (key >= NN_) v = -1e30f;
                s[jj][qi] = v;
            }
        }

        float mx0 = -1e30f, mx1 = -1e30f;
#pragma unroll
        for (int jj = 0; jj < 16; jj++) {
            mx0 = fmaxf(mx0, fmaxf(s[jj][0], s[jj][1]));
            mx1 = fmaxf(mx1, fmaxf(s[jj][2], s[jj][3]));
        }
        mx0 = fmaxf(mx0, __shfl_xor_sync(~0u, mx0, 1)); mx0 = fmaxf(mx0, __shfl_xor_sync(~0u, mx0, 2));
        mx1 = fmaxf(mx1, __shfl_xor_sync(~0u, mx1, 1)); mx1 = fmaxf(mx1, __shfl_xor_sync(~0u, mx1, 2));
        float mn0 = fmaxf(m0, mx0), mn1 = fmaxf(m1, mx1);
        float f0 = __expf(m0 - mn0), f1 = __expf(m1 - mn1);
        m0 = mn0; m1 = mn1;
        float rs0 = 0.f, rs1 = 0.f;
#pragma unroll
        for (int jj = 0; jj < 16; jj++) {
            float p0 = __expf(s[jj][0] - m0), p1 = __expf(s[jj][1] - m0);
            float p2 = __expf(s[jj][2] - m1), p3 = __expf(s[jj][3] - m1);
            s[jj][0] = p0; s[jj][1] = p1; s[jj][2] = p2; s[jj][3] = p3;
            rs0 += p0 + p1; rs1 += p2 + p3;
        }
        rs0 += __shfl_xor_sync(~0u, rs0, 1); rs0 += __shfl_xor_sync(~0u, rs0, 2);
        rs1 += __shfl_xor_sync(~0u, rs1, 1); rs1 += __shfl_xor_sync(~0u, rs1, 2);
        l0 = l0*f0 + rs0; l1 = l1*f1 + rs1;
#pragma unroll
        for (int j = 0; j < 8; j++) {
            o[j][0] *= f0; o[j][1] *= f0; o[j][2] *= f1; o[j][3] *= f1;
        }

#pragma unroll
        for (int kg = 0; kg < 8; kg++) {
            uint32_t ah[4];
            ah[0] = pack_hf2(s[2*kg][0],   s[2*kg][1]);
            ah[1] = pack_hf2(s[2*kg][2],   s[2*kg][3]);
            ah[2] = pack_hf2(s[2*kg+1][0], s[2*kg+1][1]);
            ah[3] = pack_hf2(s[2*kg+1][2], s[2*kg+1][3]);
#pragma unroll
            for (int jp = 0; jp < 4; jp++) {
                uint32_t vh[4];
                LDSM4T(vh, vb + (kg*16 + lrow)*QSTR + jp*32 + lsel*16);
                MMAH16816(o[2*jp],   ah[0],ah[1],ah[2],ah[3], vh[0], vh[1]);
                MMAH16816(o[2*jp+1], ah[0],ah[1],ah[2],ah[3], vh[2], vh[3]);
            }
        }
        __syncthreads();
    }

    const float inv0 = 1.0f / l0, inv1 = 1.0f / l1;
    const int q0 = qt*128 + wid*16 + gq, q1 = q0 + 8;
#pragma unroll
    for (int j = 0; j < 8; j++) {
        int d0 = j*8 + tq*2;
        if (q0 < NN_) {
            long long off = (long long)(b*NN_ + q0)*CC + h*DD + d0;
            *reinterpret_cast<__half2*>(aoutF + off) = __floats2half2_rn(o[j][0]*inv0, o[j][1]*inv0);
        }
        if (q1 < NN_) {
            long long off = (long long)(b*NN_ + q1)*CC + h*DD + d0;
            *reinterpret_cast<__half2*>(aoutF + off) = __floats2half2_rn(o[j][2]*inv1, o[j][3]*inv1);
        }
    }
}

// ---------------- weight fp32 -> fp16 --------------------------------------
__global__ void conv_half(const float* __restrict__ src, __half* __restrict__ dst, long long n4)
{
    long long i = (long long)blockIdx.x * blockDim.x + threadIdx.x;
    if (i >= n4) return;
    float4 v = reinterpret_cast<const float4*>(src)[i];
    __half2* d = reinterpret_cast<__half2*>(dst) + 2*i;
    d[0] = __floats2half2_rn(v.x, v.y);
    d[1] = __floats2half2_rn(v.z, v.w);
}

// ---------------- LayerNorm -> fp16 ----------------------------------------
__global__ void ln_kernel_f(const float* __restrict__ in,
                            const float* __restrict__ w, const float* __restrict__ b,
                            __half* __restrict__ outF)
{
    const long long row = blockIdx.x;
    const int tid = threadIdx.x;
    const float* rp = in + row * CC;
    float v0 = rp[tid], v1 = rp[tid+256], v2 = rp[tid+512];
    float s = v0+v1+v2, ss = v0*v0 + v1*v1 + v2*v2;
    const int wid = tid >> 5, lid = tid & 31;
    for (int o = 16; o; o >>= 1) { s += __shfl_xor_sync(~0u, s, o); ss += __shfl_xor_sync(~0u, ss, o); }
    __shared__ float rs[8], rq[8];
    if (lid == 0) { rs[wid] = s; rq[wid] = ss; }
    __syncthreads();
    float ts = 0.f, tq = 0.f;
#pragma unroll
    for (int i = 0; i < 8; i++) { ts += rs[i]; tq += rq[i]; }
    float mean = ts * (1.0f/CC);
    float rstd = rsqrtf(tq * (1.0f/CC) - mean*mean + EPS_);
#pragma unroll
    for (int k = 0; k < 3; k++) {
        int c = tid + k*256;
        float v = (k==0?v0:(k==1?v1:v2));
        outF[row*CC + c] = __float2half_rn((v - mean)*rstd * w[c] + b[c]);
    }
}

// ---------------------------------------------------------------------------
extern "C" void kernel_launch(void* const* d_in, const int* in_sizes, int n_in,
                              void* d_out, int out_size)
{
    const float* x      = (const float*)d_in[0];
    const float* attn_w = (const float*)d_in[1];
    const float* ln1_w  = (const float*)d_in[2];
    const float* ln1_b  = (const float*)d_in[3];
    const float* qkv_w  = (const float*)d_in[4];
    const float* qkv_b  = (const float*)d_in[5];
    const float* proj_w = (const float*)d_in[6];
    const float* proj_b = (const float*)d_in[7];
    const float* ln2_w  = (const float*)d_in[8];
    const float* ln2_b  = (const float*)d_in[9];
    const float* fc1_w  = (const float*)d_in[10];
    const float* fc1_b  = (const float*)d_in[11];
    const float* fc2_w  = (const float*)d_in[12];
    const float* fc2_b  = (const float*)d_in[13];

    float* out_x     = (float*)d_out;
    float* out_patch = out_x + (long long)ROWS*CC;

    __half *hlnF,*qkvwF,*projwF,*fc1wF,*fc2wF,*qkvF,*aoutF,*h2F,*fc1F;
    float *x1;
    cudaGetSymbolAddress((void**)&hlnF, g_hlnF);
    cudaGetSymbolAddress((void**)&qkvwF, g_qkvwF);
    cudaGetSymbolAddress((void**)&projwF, g_projwF);
    cudaGetSymbolAddress((void**)&fc1wF, g_fc1wF);
    cudaGetSymbolAddress((void**)&fc2wF, g_fc2wF);
    cudaGetSymbolAddress((void**)&qkvF, g_qkvF);
    cudaGetSymbolAddress((void**)&aoutF, g_aoutF);
    cudaGetSymbolAddress((void**)&x1, g_x1);
    cudaGetSymbolAddress((void**)&h2F, g_h2F);
    cudaGetSymbolAddress((void**)&fc1F, g_fc1F);

    const int SMEMHF = 2 * (128*144 + 128*144);     // 73728 (BK=64, 2-stage)
    cudaFuncSetAttribute(gemm_hf<128,0,1>, cudaFuncAttributeMaxDynamicSharedMemorySize, SMEMHF);
    cudaFuncSetAttribute(gemm_hf<128,1,1>, cudaFuncAttributeMaxDynamicSharedMemorySize, SMEMHF);
    cudaFuncSetAttribute(gemm_hf<128,2,0>, cudaFuncAttributeMaxDynamicSharedMemorySize, SMEMHF);
    cudaFuncSetAttribute(flash_attn, cudaFuncAttributeMaxDynamicSharedMemorySize, FLASH_SMEM);

    // 0) weight conversions
    conv_half<<<(int)(((long long)3*CC*CC/4 + 255)/256), 256>>>(qkv_w,  qkvwF, (long long)3*CC*CC/4);
    conv_half<<<(int)(((long long)CC*CC/4   + 255)/256), 256>>>(proj_w, projwF, (long long)CC*CC/4);
    conv_half<<<(int)(((long long)HID_*CC/4 + 255)/256), 256>>>(fc1_w,  fc1wF,  (long long)HID_*CC/4);
    conv_half<<<(int)(((long long)CC*HID_/4 + 255)/256), 256>>>(fc2_w,  fc2wF,  (long long)CC*HID_/4);

    // 1) LN1 -> fp16
    ln_kernel_f<<<ROWS, 256>>>(x, ln1_w, ln1_b, hlnF);

    // 2) qkv = hln @ qkv_w^T + qkv_b -> fp16   (K=768)
    gemm_hf<128,0,1><<<dim3(3*CC/128, (ROWS+127)/128, 1), 256, SMEMHF>>>(
        hlnF, qkvwF, nullptr, qkvF,
        ROWS, 3*CC, CC, CC, CC, 3*CC, qkv_b, nullptr, 0);

    // 3) fused flash attention -> fp16 aout + patch_attn
    flash_attn<<<dim3(5, BB*HH_), 256, FLASH_SMEM>>>(
        qkvF, attn_w, aoutF, out_patch);

    // 4) x1 = x + aout @ proj_w^T + proj_b   (K=768)
    gemm_hf<128,2,0><<<dim3(CC/128, (ROWS+127)/128, 1), 256, SMEMHF>>>(
        aoutF, projwF, x1, nullptr,
        ROWS, CC, CC, CC, CC, CC, proj_b, x, CC);

    // 5) LN2 -> fp16
    ln_kernel_f<<<ROWS, 256>>>(x1, ln2_w, ln2_b, h2F);

    // 6) fc1 = gelu(h2 @ fc1_w^T + fc1_b) -> fp16   (K=768)
    gemm_hf<128,1,1><<<dim3(HID_/128, (ROWS+127)/128, 1), 256, SMEMHF>>>(
        h2F, fc1wF, nullptr, fc1F,
        ROWS, HID_, CC, CC, CC, HID_, fc1_b, nullptr, 0);

    // 7) out = x1 + fc1 @ fc2_w^T + fc2_b   (K=3072)
    gemm_hf<128,2,0><<<dim3(CC/128, (ROWS+127)/128, 1), 256, SMEMHF>>>(
        fc1F, fc2wF, out_x, nullptr,
        ROWS, CC, HID_, HID_, HID_, CC, fc2_b, x1, CC);
}

// round 15
// speedup vs baseline: 2.8345x; 1.0109x over previous
#include <cuda_runtime.h>
#include <cuda_fp16.h>
#include <math.h>
#include <stdint.h>

// Problem constants
#define BB   32
#define NN_  577
#define CC   768
#define HH_  12
#define DD   64
#define HID_ 3072
#define ROWS (BB*NN_)                    // 18464
#define ALPHA_ 0.1f
#define EPS_ 1e-6f
#define SCALE_ 0.125f
#define L2E_ 1.44269504088896f

// ---------------- scratch --------------------------------------------------
__device__ __half g_hlnF[(long long)ROWS*CC];
__device__ __half g_qkvwF[(long long)3*CC*CC];
__device__ __half g_projwF[(long long)CC*CC];
__device__ __half g_fc1wF[(long long)HID_*CC];
__device__ __half g_fc2wF[(long long)CC*HID_];
__device__ __half g_qkvF[(long long)ROWS*3*CC];
__device__ __half g_aoutF[(long long)ROWS*CC];
__device__ float g_x1[(long long)ROWS*CC];
__device__ __half g_h2F[(long long)ROWS*CC];
__device__ __half g_fc1F[(long long)ROWS*HID_];

// =================== asm helpers ===========================================
#define MMAH16816(d, a0,a1,a2,a3, b0,b1) \
    asm volatile("mma.sync.aligned.m16n8k16.row.col.f32.f16.f16.f32 " \
        "{%0,%1,%2,%3}, {%4,%5,%6,%7}, {%8,%9}, {%0,%1,%2,%3};" \
        : "+f"((d)[0]), "+f"((d)[1]), "+f"((d)[2]), "+f"((d)[3]) \
        : "r"(a0), "r"(a1), "r"(a2), "r"(a3), "r"(b0), "r"(b1))

#define LDSM4(r, ad) \
    asm volatile("ldmatrix.sync.aligned.m8n8.x4.shared.b16 {%0,%1,%2,%3}, [%4];" \
        : "=r"((r)[0]), "=r"((r)[1]), "=r"((r)[2]), "=r"((r)[3]) : "r"(ad))

#define LDSM4T(r, ad) \
    asm volatile("ldmatrix.sync.aligned.m8n8.x4.trans.shared.b16 {%0,%1,%2,%3}, [%4];" \
        : "=r"((r)[0]), "=r"((r)[1]), "=r"((r)[2]), "=r"((r)[3]) : "r"(ad))

#define EX2H2(d, a) \
    asm volatile("ex2.approx.f16x2 %0, %1;" : "=r"(d) : "r"(a))

__device__ __forceinline__ void cpa16(uint32_t dst, const void* src, int sz) {
    asm volatile("cp.async.cg.shared.global [%0], [%1], 16, %2;" :: "r"(dst), "l"(src), "r"(sz) : "memory");
}
#define CP_COMMIT() asm volatile("cp.async.commit_group;" ::: "memory")
#define CP_WAIT1()  asm volatile("cp.async.wait_group 1;" ::: "memory")
#define CP_WAIT0()  asm volatile("cp.async.wait_group 0;" ::: "memory")

__device__ __forceinline__ uint32_t smem_u32(const void* p) {
    uint32_t a;
    asm("{ .reg .u64 t; cvta.to.shared.u64 t, %1; cvt.u32.u64 %0, t; }" : "=r"(a) : "l"(p));
    return a;
}
__device__ __forceinline__ uint32_t pack_hf2(float x, float y) {
    __half2 h = __floats2half2_rn(x, y);
    return *reinterpret_cast<uint32_t*>(&h);
}

// =================== single-pass fp16 HMMA GEMM (BK=64) ====================
// C = epi(A @ B^T + bias); A [M,K] fp16 ldA, B [N,K] fp16 ldB.
// BK=64 per stage, row stride 144 B. K % 64 == 0.
// EPI: 0 none, 1 exact GELU, 2 +Res.  OUTF: 0 fp32 C, 1 fp16 CF.
template<int BN, int EPI, int OUTF>
__global__ void __launch_bounds__(256, 2)
gemm_hf(const __half* __restrict__ A, const __half* __restrict__ B,
        float* __restrict__ C, __half* __restrict__ CF,
        int M, int N, int K, int ldA, int ldB, int ldC,
        const float* __restrict__ bias,
        const float* __restrict__ Res, int ldRes)
{
    constexpr int RSTR   = 144;
    constexpr int ABYTES = 128 * RSTR;
    constexpr int BBYTES = BN * RSTR;
    constexpr int STAGE  = ABYTES + BBYTES;
    constexpr int NT     = BN / 16;
    constexpr int BPASS  = BN / 32;

    const int tid = threadIdx.x, lane = tid & 31, wid = tid >> 5;
    const int gq = lane >> 2, tq = lane & 3;
    const int warp_m = wid & 3, warp_n = wid >> 2;

    const int rowBase = blockIdx.y * 128;
    const int colBase = blockIdx.x * BN;

    extern __shared__ char smraw[];
    const uint32_t smb = smem_u32(smraw);

    float acc[2][NT][4];
#pragma unroll
    for (int i = 0; i < 2; i++)
#pragma unroll
        for (int j = 0; j < NT; j++)
#pragma unroll
            for (int q = 0; q < 4; q++) acc[i][j][q] = 0.f;

    const int nst = K / 64;

    auto load_stage = [&](int s) {
        const int k0 = s * 64;
        const uint32_t base = smb + (s & 1) * STAGE;
#pragma unroll
        for (int i = 0; i < 4; i++) {
            int cid = tid + i*256;
            int row = cid >> 3, q = cid & 7;
            int gr = rowBase + row;
            int sz = (gr < M) ? 16 : 0;
            long long go = (long long)(gr < M ? gr : 0) * ldA + k0 + q*8;
            cpa16(base + row*RSTR + q*16, A + go, sz);
        }
#pragma unroll
        for (int i = 0; i < BPASS; i++) {
            int cid = tid + i*256;
            int row = cid >> 3, q = cid & 7;
            int gn = colBase + row;
            int sz = (gn < N) ? 16 : 0;
            long long go = (long long)(gn < N ? gn : 0) * ldB + k0 + q*8;
            cpa16(base + ABYTES + row*RSTR + q*16, B + go, sz);
        }
    };

    const uint32_t lrow = lane & 15, lsel = lane >> 4;
    const uint32_t aOff = (warp_m*32 + lrow)*RSTR + lsel*16;
    const uint32_t bOff = (warp_n*(BN/2) + lrow)*RSTR + lsel*16;

    load_stage(0);
    CP_COMMIT();

    for (int s = 0; s < nst; s++) {
        if (s + 1 < nst) { load_stage(s + 1); CP_COMMIT(); CP_WAIT1(); }
        else             { CP_WAIT0(); }
        __syncthreads();

        const uint32_t st = smb + (s & 1) * STAGE;
#pragma unroll
        for (int ks = 0; ks < 4; ks++) {
            uint32_t a[2][4];
#pragma unroll
            for (int i = 0; i < 2; i++)
                LDSM4(a[i], st + aOff + i*16*RSTR + ks*32);
#pragma unroll
            for (int j2 = 0; j2 < NT/2; j2++) {
                uint32_t bf[4];
                LDSM4(bf, st + ABYTES + bOff + j2*16*RSTR + ks*32);
#pragma unroll
                for (int i = 0; i < 2; i++) {
                    MMAH16816(acc[i][2*j2],   a[i][0],a[i][1],a[i][2],a[i][3], bf[0], bf[2]);
                    MMAH16816(acc[i][2*j2+1], a[i][0],a[i][1],a[i][2],a[i][3], bf[1], bf[3]);
                }
            }
        }
        __syncthreads();
    }

#pragma unroll
    for (int i = 0; i < 2; i++) {
#pragma unroll
        for (int half = 0; half < 2; half++) {
            const int r = rowBase + warp_m*32 + i*16 + gq + half*8;
            if (r >= M) continue;
#pragma unroll
            for (int j = 0; j < NT; j++) {
                const int c0 = colBase + warp_n*(BN/2) + j*8 + tq*2;
                float v0 = acc[i][j][half*2 + 0];
                float v1 = acc[i][j][half*2 + 1];
                if (bias) { v0 += bias[c0]; v1 += (c0+1 < N) ? bias[c0+1] : 0.f; }
                if (EPI == 1) {
                    v0 = 0.5f*v0*(1.0f + erff(v0*0.70710678118654752f));
                    v1 = 0.5f*v1*(1.0f + erff(v1*0.70710678118654752f));
                } else if (EPI == 2) {
                    v0 += Res[(long long)r*ldRes + c0];
                    if (c0+1 < N) v1 += Res[(long long)r*ldRes + c0 + 1];
                }
                if (OUTF) {
                    if (c0 + 1 < N) {
                        *reinterpret_cast<__half2*>(CF + (long long)r*ldC + c0) = __floats2half2_rn(v0, v1);
                    } else if (c0 < N) {
                        CF[(long long)r*ldC + c0] = __float2half_rn(v0);
                    }
                } else {
                    if (c0 < N)     C[(long long)r*ldC + c0]     = v0;
                    if (c0+1 < N)   C[(long long)r*ldC + c0 + 1] = v1;
                }
            }
        }
    }
}

// =================== fused flash attention (fp16, h2 exp) ==================
#define QSTR 144
#define QB   18432
#define KBASE QB
#define VBASE (QB + 2*QB)
#define FLASH_SMEM (VBASE + 2*QB)   // 92160

__global__ void __launch_bounds__(256, 1)
flash_attn(const __half* __restrict__ qkvF,
           const float* __restrict__ attn_w,
           __half* __restrict__ aoutF,
           float* __restrict__ patch_out)
{
    const int z = blockIdx.y, qt = blockIdx.x;
    const int b = z / HH_, h = z % HH_;
    const int tid = threadIdx.x, lane = tid & 31, wid = tid >> 5;
    const int gq = lane >> 2, tq = lane & 3;

    extern __shared__ char smraw[];
    const uint32_t smb = smem_u32(smraw);

#pragma unroll
    for (int i = 0; i < 4; i++) {
        int cid = tid + i*256;
        int row = cid >> 3, ch = cid & 7;
        int gr = qt*128 + row;
        int sz = (gr < NN_) ? 16 : 0;
        long long go = (long long)(b*NN_ + (gr < NN_ ? gr : 0))*(3*CC) + h*DD + ch*8;
        cpa16(smb + row*QSTR + ch*16, qkvF + go, sz);
    }
    auto load_kv = [&](int t) {
        const uint32_t kb = smb + KBASE + (t & 1)*QB;
        const uint32_t vb = smb + VBASE + (t & 1)*QB;
#pragma unroll
        for (int i = 0; i < 4; i++) {
            int cid = tid + i*256;
            int row = cid >> 3, ch = cid & 7;
            int gk = t*128 + row;
            int sz = (gk < NN_) ? 16 : 0;
            long long base = (long long)(b*NN_ + (gk < NN_ ? gk : 0))*(3*CC) + h*DD + ch*8;
            cpa16(kb + row*QSTR + ch*16, qkvF + base + CC,   sz);
            cpa16(vb + row*QSTR + ch*16, qkvF + base + 2*CC, sz);
        }
    };

    float o[8][4];
#pragma unroll
    for (int j = 0; j < 8; j++)
#pragma unroll
        for (int q = 0; q < 4; q++) o[j][q] = 0.f;
    float m0 = -INFINITY, m1 = -INFINITY, l0 = 0.f, l1 = 0.f;

    const uint32_t lrow = lane & 15, lsel = lane >> 4;
    const uint32_t qOff = (wid*16 + lrow)*QSTR + lsel*16;
    const bool clsrow = (qt == 0) && (wid == 0) && (gq == 0);

    load_kv(0);
    CP_COMMIT();

    for (int t = 0; t < 5; t++) {
        if (t < 4) { load_kv(t + 1); CP_COMMIT(); CP_WAIT1(); }
        else       { CP_WAIT0(); }
        __syncthreads();

        const uint32_t kb = smb + KBASE + (t & 1)*QB;
        const uint32_t vb = smb + VBASE + (t & 1)*QB;

        // ---- S = Q @ K^T ----
        float s[16][4];
#pragma unroll
        for (int j = 0; j < 16; j++)
#pragma unroll
            for (int q = 0; q < 4; q++) s[j][q] = 0.f;

#pragma unroll
        for (int kg = 0; kg < 4; kg++) {
            uint32_t qh[4];
            LDSM4(qh, smb + qOff + kg*32);
#pragma unroll
            for (int jj = 0; jj < 8; jj++) {
                uint32_t kh[4];
                LDSM4(kh, kb + (jj*16 + lrow)*QSTR + lsel*16 + kg*32);
                MMAH16816(s[2*jj],   qh[0],qh[1],qh[2],qh[3], kh[0], kh[2]);
                MMAH16816(s[2*jj+1], qh[0],qh[1],qh[2],qh[3], kh[1], kh[3]);
            }
        }

        // ---- scale + CLS factor + patch + mask ----
#pragma unroll
        for (int jj = 0; jj < 16; jj++) {
#pragma unroll
            for (int qi = 0; qi < 4; qi++) {
                float v = s[jj][qi] * SCALE_;
                int key = t*128 + jj*8 + tq*2 + (qi & 1);
                if (clsrow && qi < 2) {
                    if (key >= 1 && key < NN_) {
                        patch_out[(long long)z*(NN_-1) + key - 1] = v;
                        v *= attn_w[(long long)b*(NN_-1) + key - 1] * ALPHA_ + (1.0f - ALPHA_);
                    }
                }
                if (key >= NN_) v = -1e30f;
                s[jj][qi] = v;
            }
        }

        // ---- online softmax (exp in fp16x2; result IS the PV fragment) ----
        float mx0 = -1e30f, mx1 = -1e30f;
#pragma unroll
        for (int jj = 0; jj < 16; jj++) {
            mx0 = fmaxf(mx0, fmaxf(s[jj][0], s[jj][1]));
            mx1 = fmaxf(mx1, fmaxf(s[jj][2], s[jj][3]));
        }
        mx0 = fmaxf(mx0, __shfl_xor_sync(~0u, mx0, 1)); mx0 = fmaxf(mx0, __shfl_xor_sync(~0u, mx0, 2));
        mx1 = fmaxf(mx1, __shfl_xor_sync(~0u, mx1, 1)); mx1 = fmaxf(mx1, __shfl_xor_sync(~0u, mx1, 2));
        float mn0 = fmaxf(m0, mx0), mn1 = fmaxf(m1, mx1);
        float f0 = __expf(m0 - mn0), f1 = __expf(m1 - mn1);
        m0 = mn0; m1 = mn1;

        uint32_t ps[16][2];
        float rs0 = 0.f, rs1 = 0.f;
#pragma unroll
        for (int jj = 0; jj < 16; jj++) {
            float a0 = (s[jj][0] - m0) * L2E_;
            float a1 = (s[jj][1] - m0) * L2E_;
            float a2 = (s[jj][2] - m1) * L2E_;
            float a3 = (s[jj][3] - m1) * L2E_;
            uint32_t t0 = pack_hf2(a0, a1), t1 = pack_hf2(a2, a3);
            uint32_t p0, p1;
            EX2H2(p0, t0);
            EX2H2(p1, t1);
            ps[jj][0] = p0; ps[jj][1] = p1;
            float2 fa = __half22float2(*reinterpret_cast<__half2*>(&p0));
            float2 fb = __half22float2(*reinterpret_cast<__half2*>(&p1));
            rs0 += fa.x + fa.y; rs1 += fb.x + fb.y;
        }
        rs0 += __shfl_xor_sync(~0u, rs0, 1); rs0 += __shfl_xor_sync(~0u, rs0, 2);
        rs1 += __shfl_xor_sync(~0u, rs1, 1); rs1 += __shfl_xor_sync(~0u, rs1, 2);
        l0 = l0*f0 + rs0; l1 = l1*f1 + rs1;
#pragma unroll
        for (int j = 0; j < 8; j++) {
            o[j][0] *= f0; o[j][1] *= f0; o[j][2] *= f1; o[j][3] *= f1;
        }

        // ---- O += P @ V (P already fp16; V key-major, trans ldmatrix) ----
#pragma unroll
        for (int kg = 0; kg < 8; kg++) {
            const uint32_t a0 = ps[2*kg][0],   a1 = ps[2*kg][1];
            const uint32_t a2 = ps[2*kg+1][0], a3 = ps[2*kg+1][1];
#pragma unroll
            for (int jp = 0; jp < 4; jp++) {
                uint32_t vh[4];
                LDSM4T(vh, vb + (kg*16 + lrow)*QSTR + jp*32 + lsel*16);
                MMAH16816(o[2*jp],   a0,a1,a2,a3, vh[0], vh[1]);
                MMAH16816(o[2*jp+1], a0,a1,a2,a3, vh[2], vh[3]);
            }
        }
        __syncthreads();
    }

    // ---- epilogue ----
    const float inv0 = 1.0f / l0, inv1 = 1.0f / l1;
    const int q0 = qt*128 + wid*16 + gq, q1 = q0 + 8;
#pragma unroll
    for (int j = 0; j < 8; j++) {
        int d0 = j*8 + tq*2;
        if (q0 < NN_) {
            long long off = (long long)(b*NN_ + q0)*CC + h*DD + d0;
            *reinterpret_cast<__half2*>(aoutF + off) = __floats2half2_rn(o[j][0]*inv0, o[j][1]*inv0);
        }
        if (q1 < NN_) {
            long long off = (long long)(b*NN_ + q1)*CC + h*DD + d0;
            *reinterpret_cast<__half2*>(aoutF + off) = __floats2half2_rn(o[j][2]*inv1, o[j][3]*inv1);
        }
    }
}

// ---------------- fused weight fp32 -> fp16 (all 4 weights, 1 launch) ------
__global__ void conv_all(const float* __restrict__ s0, __half* __restrict__ d0, long long n0,
                         const float* __restrict__ s1, __half* __restrict__ d1, long long n1,
                         const float* __restrict__ s2, __half* __restrict__ d2, long long n2,
                         const float* __restrict__ s3, __half* __restrict__ d3, long long n3)
{
    long long i = (long long)blockIdx.x * blockDim.x + threadIdx.x;
    const float* s; __half* d; long long off;
    if      (i < n0)          { s = s0; d = d0; off = i; }
    else if (i < n0+n1)       { s = s1; d = d1; off = i - n0; }
    else if (i < n0+n1+n2)    { s = s2; d = d2; off = i - n0 - n1; }
    else if (i < n0+n1+n2+n3) { s = s3; d = d3; off = i - n0 - n1 - n2; }
    else return;
    float4 v = reinterpret_cast<const float4*>(s)[off];
    __half2* dp = reinterpret_cast<__half2*>(d) + 2*off;
    dp[0] = __floats2half2_rn(v.x, v.y);
    dp[1] = __floats2half2_rn(v.z, v.w);
}

// ---------------- LayerNorm -> fp16 ----------------------------------------
__global__ void ln_kernel_f(const float* __restrict__ in,
                            const float* __restrict__ w, const float* __restrict__ b,
                            __half* __restrict__ outF)
{
    const long long row = blockIdx.x;
    const int tid = threadIdx.x;
    const float* rp = in + row * CC;
    float v0 = rp[tid], v1 = rp[tid+256], v2 = rp[tid+512];
    float s = v0+v1+v2, ss = v0*v0 + v1*v1 + v2*v2;
    const int wid = tid >> 5, lid = tid & 31;
    for (int o = 16; o; o >>= 1) { s += __shfl_xor_sync(~0u, s, o); ss += __shfl_xor_sync(~0u, ss, o); }
    __shared__ float rs[8], rq[8];
    if (lid == 0) { rs[wid] = s; rq[wid] = ss; }
    __syncthreads();
    float ts = 0.f, tq = 0.f;
#pragma unroll
    for (int i = 0; i < 8; i++) { ts += rs[i]; tq += rq[i]; }
    float mean = ts * (1.0f/CC);
    float rstd = rsqrtf(tq * (1.0f/CC) - mean*mean + EPS_);
#pragma unroll
    for (int k = 0; k < 3; k++) {
        int c = tid + k*256;
        float v = (k==0?v0:(k==1?v1:v2));
        outF[row*CC + c] = __float2half_rn((v - mean)*rstd * w[c] + b[c]);
    }
}

// ---------------------------------------------------------------------------
extern "C" void kernel_launch(void* const* d_in, const int* in_sizes, int n_in,
                              void* d_out, int out_size)
{
    const float* x      = (const float*)d_in[0];
    const float* attn_w = (const float*)d_in[1];
    const float* ln1_w  = (const float*)d_in[2];
    const float* ln1_b  = (const float*)d_in[3];
    const float* qkv_w  = (const float*)d_in[4];
    const float* qkv_b  = (const float*)d_in[5];
    const float* proj_w = (const float*)d_in[6];
    const float* proj_b = (const float*)d_in[7];
    const float* ln2_w  = (const float*)d_in[8];
    const float* ln2_b  = (const float*)d_in[9];
    const float* fc1_w  = (const float*)d_in[10];
    const float* fc1_b  = (const float*)d_in[11];
    const float* fc2_w  = (const float*)d_in[12];
    const float* fc2_b  = (const float*)d_in[13];

    float* out_x     = (float*)d_out;
    float* out_patch = out_x + (long long)ROWS*CC;

    __half *hlnF,*qkvwF,*projwF,*fc1wF,*fc2wF,*qkvF,*aoutF,*h2F,*fc1F;
    float *x1;
    cudaGetSymbolAddress((void**)&hlnF, g_hlnF);
    cudaGetSymbolAddress((void**)&qkvwF, g_qkvwF);
    cudaGetSymbolAddress((void**)&projwF, g_projwF);
    cudaGetSymbolAddress((void**)&fc1wF, g_fc1wF);
    cudaGetSymbolAddress((void**)&fc2wF, g_fc2wF);
    cudaGetSymbolAddress((void**)&qkvF, g_qkvF);
    cudaGetSymbolAddress((void**)&aoutF, g_aoutF);
    cudaGetSymbolAddress((void**)&x1, g_x1);
    cudaGetSymbolAddress((void**)&h2F, g_h2F);
    cudaGetSymbolAddress((void**)&fc1F, g_fc1F);

    const int SMEMHF = 2 * (128*144 + 128*144);     // 73728 (BK=64, 2-stage)
    cudaFuncSetAttribute(gemm_hf<128,0,1>, cudaFuncAttributeMaxDynamicSharedMemorySize, SMEMHF);
    cudaFuncSetAttribute(gemm_hf<128,1,1>, cudaFuncAttributeMaxDynamicSharedMemorySize, SMEMHF);
    cudaFuncSetAttribute(gemm_hf<128,2,0>, cudaFuncAttributeMaxDynamicSharedMemorySize, SMEMHF);
    cudaFuncSetAttribute(flash_attn, cudaFuncAttributeMaxDynamicSharedMemorySize, FLASH_SMEM);

    // 0) all weight conversions in one launch
    const long long n0 = (long long)3*CC*CC/4, n1 = (long long)CC*CC/4;
    const long long n2 = (long long)HID_*CC/4, n3 = (long long)CC*HID_/4;
    conv_all<<<(int)((n0+n1+n2+n3 + 255)/256), 256>>>(
        qkv_w, qkvwF, n0, proj_w, projwF, n1, fc1_w, fc1wF, n2, fc2_w, fc2wF, n3);

    // 1) LN1 -> fp16
    ln_kernel_f<<<ROWS, 256>>>(x, ln1_w, ln1_b, hlnF);

    // 2) qkv = hln @ qkv_w^T + qkv_b -> fp16   (K=768)
    gemm_hf<128,0,1><<<dim3(3*CC/128, (ROWS+127)/128, 1), 256, SMEMHF>>>(
        hlnF, qkvwF, nullptr, qkvF,
        ROWS, 3*CC, CC, CC, CC, 3*CC, qkv_b, nullptr, 0);

    // 3) fused flash attention -> fp16 aout + patch_attn
    flash_attn<<<dim3(5, BB*HH_), 256, FLASH_SMEM>>>(
        qkvF, attn_w, aoutF, out_patch);

    // 4) x1 = x + aout @ proj_w^T + proj_b   (K=768)
    gemm_hf<128,2,0><<<dim3(CC/128, (ROWS+127)/128, 1), 256, SMEMHF>>>(
        aoutF, projwF, x1, nullptr,
        ROWS, CC, CC, CC, CC, CC, proj_b, x, CC);

    // 5) LN2 -> fp16
    ln_kernel_f<<<ROWS, 256>>>(x1, ln2_w, ln2_b, h2F);

    // 6) fc1 = gelu(h2 @ fc1_w^T + fc1_b) -> fp16   (K=768)
    gemm_hf<128,1,1><<<dim3(HID_/128, (ROWS+127)/128, 1), 256, SMEMHF>>>(
        h2F, fc1wF, nullptr, fc1F,
        ROWS, HID_, CC, CC, CC, HID_, fc1_b, nullptr, 0);

    // 7) out = x1 + fc1 @ fc2_w^T + fc2_b   (K=3072)
    gemm_hf<128,2,0><<<dim3(CC/128, (ROWS+127)/128, 1), 256, SMEMHF>>>(
        fc1F, fc2wF, out_x, nullptr,
        ROWS, CC, HID_, HID_, HID_, CC, fc2_b, x1, CC);
}

// round 17
// speedup vs baseline: 2.8791x; 1.0157x over previous
#include <cuda_runtime.h>
#include <cuda_fp16.h>
#include <math.h>
#include <stdint.h>

// Problem constants
#define BB   32
#define NN_  577
#define CC   768
#define HH_  12
#define DD   64
#define HID_ 3072
#define ROWS (BB*NN_)                    // 18464
#define ALPHA_ 0.1f
#define EPS_ 1e-6f
#define SCALE_ 0.125f
#define L2E_ 1.44269504088896f

// ---------------- scratch --------------------------------------------------
__device__ __half g_hlnF[(long long)ROWS*CC];
__device__ __half g_qkvwF[(long long)3*CC*CC];
__device__ __half g_projwF[(long long)CC*CC];
__device__ __half g_fc1wF[(long long)HID_*CC];
__device__ __half g_fc2wF[(long long)CC*HID_];
__device__ __half g_qkvF[(long long)ROWS*3*CC];
__device__ __half g_aoutF[(long long)ROWS*CC];
__device__ float g_x1[(long long)ROWS*CC];
__device__ __half g_h2F[(long long)ROWS*CC];
__device__ __half g_fc1F[(long long)ROWS*HID_];

// =================== asm helpers ===========================================
#define MMAH16816(d, a0,a1,a2,a3, b0,b1) \
    asm volatile("mma.sync.aligned.m16n8k16.row.col.f32.f16.f16.f32 " \
        "{%0,%1,%2,%3}, {%4,%5,%6,%7}, {%8,%9}, {%0,%1,%2,%3};" \
        : "+f"((d)[0]), "+f"((d)[1]), "+f"((d)[2]), "+f"((d)[3]) \
        : "r"(a0), "r"(a1), "r"(a2), "r"(a3), "r"(b0), "r"(b1))

#define LDSM4(r, ad) \
    asm volatile("ldmatrix.sync.aligned.m8n8.x4.shared.b16 {%0,%1,%2,%3}, [%4];" \
        : "=r"((r)[0]), "=r"((r)[1]), "=r"((r)[2]), "=r"((r)[3]) : "r"(ad))

#define LDSM4T(r, ad) \
    asm volatile("ldmatrix.sync.aligned.m8n8.x4.trans.shared.b16 {%0,%1,%2,%3}, [%4];" \
        : "=r"((r)[0]), "=r"((r)[1]), "=r"((r)[2]), "=r"((r)[3]) : "r"(ad))

#define EX2H2(d, a) \
    asm volatile("ex2.approx.f16x2 %0, %1;" : "=r"(d) : "r"(a))

__device__ __forceinline__ void cpa16(uint32_t dst, const void* src, int sz) {
    asm volatile("cp.async.cg.shared.global [%0], [%1], 16, %2;" :: "r"(dst), "l"(src), "r"(sz) : "memory");
}
#define CP_COMMIT() asm volatile("cp.async.commit_group;" ::: "memory")
#define CP_WAIT1()  asm volatile("cp.async.wait_group 1;" ::: "memory")
#define CP_WAIT0()  asm volatile("cp.async.wait_group 0;" ::: "memory")

__device__ __forceinline__ uint32_t smem_u32(const void* p) {
    uint32_t a;
    asm("{ .reg .u64 t; cvta.to.shared.u64 t, %1; cvt.u32.u64 %0, t; }" : "=r"(a) : "l"(p));
    return a;
}
__device__ __forceinline__ uint32_t pack_hf2(float x, float y) {
    __half2 h = __floats2half2_rn(x, y);
    return *reinterpret_cast<uint32_t*>(&h);
}

// ============ single-pass fp16 HMMA GEMM (BK=64, 3-stage, 1 sync) ==========
// C = epi(A @ B^T + bias); A [M,K] fp16 ldA, B [N,K] fp16 ldB.  K % 64 == 0.
// EPI: 0 none, 1 exact GELU, 2 +Res.  OUTF: 0 fp32 C, 1 fp16 CF.
template<int BN, int EPI, int OUTF>
__global__ void __launch_bounds__(256, 2)
gemm_hf(const __half* __restrict__ A, const __half* __restrict__ B,
        float* __restrict__ C, __half* __restrict__ CF,
        int M, int N, int K, int ldA, int ldB, int ldC,
        const float* __restrict__ bias,
        const float* __restrict__ Res, int ldRes)
{
    constexpr int RSTR   = 144;
    constexpr int ABYTES = 128 * RSTR;
    constexpr int BBYTES = BN * RSTR;
    constexpr int STAGE  = ABYTES + BBYTES;      // 36864 for BN=128
    constexpr int NT     = BN / 16;
    constexpr int BPASS  = BN / 32;

    const int tid = threadIdx.x, lane = tid & 31, wid = tid >> 5;
    const int gq = lane >> 2, tq = lane & 3;
    const int warp_m = wid & 3, warp_n = wid >> 2;

    const int rowBase = blockIdx.y * 128;
    const int colBase = blockIdx.x * BN;

    extern __shared__ char smraw[];
    const uint32_t smb = smem_u32(smraw);

    float acc[2][NT][4];
#pragma unroll
    for (int i = 0; i < 2; i++)
#pragma unroll
        for (int j = 0; j < NT; j++)
#pragma unroll
            for (int q = 0; q < 4; q++) acc[i][j][q] = 0.f;

    const int nst = K / 64;

    auto load_stage = [&](int s) {
        const int k0 = s * 64;
        const uint32_t base = smb + (s % 3) * STAGE;
#pragma unroll
        for (int i = 0; i < 4; i++) {
            int cid = tid + i*256;
            int row = cid >> 3, q = cid & 7;
            int gr = rowBase + row;
            int sz = (gr < M) ? 16 : 0;
            long long go = (long long)(gr < M ? gr : 0) * ldA + k0 + q*8;
            cpa16(base + row*RSTR + q*16, A + go, sz);
        }
#pragma unroll
        for (int i = 0; i < BPASS; i++) {
            int cid = tid + i*256;
            int row = cid >> 3, q = cid & 7;
            int gn = colBase + row;
            int sz = (gn < N) ? 16 : 0;
            long long go = (long long)(gn < N ? gn : 0) * ldB + k0 + q*8;
            cpa16(base + ABYTES + row*RSTR + q*16, B + go, sz);
        }
    };

    const uint32_t lrow = lane & 15, lsel = lane >> 4;
    const uint32_t aOff = (warp_m*32 + lrow)*RSTR + lsel*16;
    const uint32_t bOff = (warp_n*(BN/2) + lrow)*RSTR + lsel*16;

    load_stage(0); CP_COMMIT();
    if (nst > 1) { load_stage(1); CP_COMMIT(); }

    for (int s = 0; s < nst; s++) {
        if (s + 1 < nst) CP_WAIT1(); else CP_WAIT0();
        __syncthreads();
        // buffer (s-1)%3 == (s+2)%3 is free: all warps finished compute(s-1)
        if (s + 2 < nst) { load_stage(s + 2); CP_COMMIT(); }

        const uint32_t st = smb + (s % 3) * STAGE;
#pragma unroll
        for (int ks = 0; ks < 4; ks++) {
            uint32_t a[2][4];
#pragma unroll
            for (int i = 0; i < 2; i++)
                LDSM4(a[i], st + aOff + i*16*RSTR + ks*32);
#pragma unroll
            for (int j2 = 0; j2 < NT/2; j2++) {
                uint32_t bf[4];
                LDSM4(bf, st + ABYTES + bOff + j2*16*RSTR + ks*32);
#pragma unroll
                for (int i = 0; i < 2; i++) {
                    MMAH16816(acc[i][2*j2],   a[i][0],a[i][1],a[i][2],a[i][3], bf[0], bf[2]);
                    MMAH16816(acc[i][2*j2+1], a[i][0],a[i][1],a[i][2],a[i][3], bf[1], bf[3]);
                }
            }
        }
    }

#pragma unroll
    for (int i = 0; i < 2; i++) {
#pragma unroll
        for (int half = 0; half < 2; half++) {
            const int r = rowBase + warp_m*32 + i*16 + gq + half*8;
            if (r >= M) continue;
#pragma unroll
            for (int j = 0; j < NT; j++) {
                const int c0 = colBase + warp_n*(BN/2) + j*8 + tq*2;
                float v0 = acc[i][j][half*2 + 0];
                float v1 = acc[i][j][half*2 + 1];
                if (bias) { v0 += bias[c0]; v1 += (c0+1 < N) ? bias[c0+1] : 0.f; }
                if (EPI == 1) {
                    v0 = 0.5f*v0*(1.0f + erff(v0*0.70710678118654752f));
                    v1 = 0.5f*v1*(1.0f + erff(v1*0.70710678118654752f));
                } else if (EPI == 2) {
                    v0 += Res[(long long)r*ldRes + c0];
                    if (c0+1 < N) v1 += Res[(long long)r*ldRes + c0 + 1];
                }
                if (OUTF) {
                    if (c0 + 1 < N) {
                        *reinterpret_cast<__half2*>(CF + (long long)r*ldC + c0) = __floats2half2_rn(v0, v1);
                    } else if (c0 < N) {
                        CF[(long long)r*ldC + c0] = __float2half_rn(v0);
                    }
                } else {
                    if (c0 < N)     C[(long long)r*ldC + c0]     = v0;
                    if (c0+1 < N)   C[(long long)r*ldC + c0 + 1] = v1;
                }
            }
        }
    }
}

// ======= fused flash attention (fp16, KV tile 64, 2 CTA/SM) ================
#define QSTR 144
#define QB   18432             // Q: 128*144
#define KVB  9216              // K/V stage: 64*144
#define KBASE QB
#define VBASE (QB + 2*KVB)     // 36864
#define FLASH_SMEM (VBASE + 2*KVB)   // 55296

__global__ void __launch_bounds__(256, 2)
flash_attn(const __half* __restrict__ qkvF,
           const float* __restrict__ attn_w,
           __half* __restrict__ aoutF,
           float* __restrict__ patch_out)
{
    const int z = blockIdx.y, qt = blockIdx.x;
    const int b = z / HH_, h = z % HH_;
    const int tid = threadIdx.x, lane = tid & 31, wid = tid >> 5;
    const int gq = lane >> 2, tq = lane & 3;

    extern __shared__ char smraw[];
    const uint32_t smb = smem_u32(smraw);

    // ---- load Q tile (once) ----
#pragma unroll
    for (int i = 0; i < 4; i++) {
        int cid = tid + i*256;
        int row = cid >> 3, ch = cid & 7;
        int gr = qt*128 + row;
        int sz = (gr < NN_) ? 16 : 0;
        long long go = (long long)(b*NN_ + (gr < NN_ ? gr : 0))*(3*CC) + h*DD + ch*8;
        cpa16(smb + row*QSTR + ch*16, qkvF + go, sz);
    }
    auto load_kv = [&](int t) {
        const uint32_t kb = smb + KBASE + (t & 1)*KVB;
        const uint32_t vb = smb + VBASE + (t & 1)*KVB;
#pragma unroll
        for (int i = 0; i < 2; i++) {
            int cid = tid + i*256;
            int row = cid >> 3, ch = cid & 7;          // row 0..63
            int gk = t*64 + row;
            int sz = (gk < NN_) ? 16 : 0;
            long long base = (long long)(b*NN_ + (gk < NN_ ? gk : 0))*(3*CC) + h*DD + ch*8;
            cpa16(kb + row*QSTR + ch*16, qkvF + base + CC,   sz);
            cpa16(vb + row*QSTR + ch*16, qkvF + base + 2*CC, sz);
        }
    };

    float o[8][4];
#pragma unroll
    for (int j = 0; j < 8; j++)
#pragma unroll
        for (int q = 0; q < 4; q++) o[j][q] = 0.f;
    float m0 = -INFINITY, m1 = -INFINITY, l0 = 0.f, l1 = 0.f;

    const uint32_t lrow = lane & 15, lsel = lane >> 4;
    const uint32_t qOff = (wid*16 + lrow)*QSTR + lsel*16;
    const bool clsrow = (qt == 0) && (wid == 0) && (gq == 0);

    load_kv(0);
    CP_COMMIT();

    for (int t = 0; t < 10; t++) {                 // 10 tiles of 64 keys
        if (t < 9) { load_kv(t + 1); CP_COMMIT(); CP_WAIT1(); }
        else       { CP_WAIT0(); }
        __syncthreads();

        const uint32_t kb = smb + KBASE + (t & 1)*KVB;
        const uint32_t vb = smb + VBASE + (t & 1)*KVB;

        // ---- S = Q @ K^T (64 keys) ----
        float s[8][4];
#pragma unroll
        for (int j = 0; j < 8; j++)
#pragma unroll
            for (int q = 0; q < 4; q++) s[j][q] = 0.f;

#pragma unroll
        for (int kg = 0; kg < 4; kg++) {
            uint32_t qh[4];
            LDSM4(qh, smb + qOff + kg*32);
#pragma unroll
            for (int jj = 0; jj < 4; jj++) {
                uint32_t kh[4];
                LDSM4(kh, kb + (jj*16 + lrow)*QSTR + lsel*16 + kg*32);
                MMAH16816(s[2*jj],   qh[0],qh[1],qh[2],qh[3], kh[0], kh[2]);
                MMAH16816(s[2*jj+1], qh[0],qh[1],qh[2],qh[3], kh[1], kh[3]);
            }
        }

        // ---- scale + CLS factor + patch + mask ----
#pragma unroll
        for (int jj = 0; jj < 8; jj++) {
#pragma unroll
            for (int qi = 0; qi < 4; qi++) {
                float v = s[jj][qi] * SCALE_;
                int key = t*64 + jj*8 + tq*2 + (qi & 1);
                if (clsrow && qi < 2) {
                    if (key >= 1 && key < NN_) {
                        patch_out[(long long)z*(NN_-1) + key - 1] = v;
                        v *= attn_w[(long long)b*(NN_-1) + key - 1] * ALPHA_ + (1.0f - ALPHA_);
                    }
                }
                if (key >= NN_) v = -1e30f;
                s[jj][qi] = v;
            }
        }

        // ---- online softmax (fp16x2 exp; result IS the PV fragment) ----
        float mx0 = -1e30f, mx1 = -1e30f;
#pragma unroll
        for (int jj = 0; jj < 8; jj++) {
            mx0 = fmaxf(mx0, fmaxf(s[jj][0], s[jj][1]));
            mx1 = fmaxf(mx1, fmaxf(s[jj][2], s[jj][3]));
        }
        mx0 = fmaxf(mx0, __shfl_xor_sync(~0u, mx0, 1)); mx0 = fmaxf(mx0, __shfl_xor_sync(~0u, mx0, 2));
        mx1 = fmaxf(mx1, __shfl_xor_sync(~0u, mx1, 1)); mx1 = fmaxf(mx1, __shfl_xor_sync(~0u, mx1, 2));
        float mn0 = fmaxf(m0, mx0), mn1 = fmaxf(m1, mx1);
        float f0 = __expf(m0 - mn0), f1 = __expf(m1 - mn1);
        m0 = mn0; m1 = mn1;

        uint32_t ps[8][2];
        float rs0 = 0.f, rs1 = 0.f;
#pragma unroll
        for (int jj = 0; jj < 8; jj++) {
            float a0 = (s[jj][0] - m0) * L2E_;
            float a1 = (s[jj][1] - m0) * L2E_;
            float a2 = (s[jj][2] - m1) * L2E_;
            float a3 = (s[jj][3] - m1) * L2E_;
            uint32_t t0 = pack_hf2(a0, a1), t1 = pack_hf2(a2, a3);
            uint32_t p0, p1;
            EX2H2(p0, t0);
            EX2H2(p1, t1);
            ps[jj][0] = p0; ps[jj][1] = p1;
            float2 fa = __half22float2(*reinterpret_cast<__half2*>(&p0));
            float2 fb = __half22float2(*reinterpret_cast<__half2*>(&p1));
            rs0 += fa.x + fa.y; rs1 += fb.x + fb.y;
        }
        rs0 += __shfl_xor_sync(~0u, rs0, 1); rs0 += __shfl_xor_sync(~0u, rs0, 2);
        rs1 += __shfl_xor_sync(~0u, rs1, 1); rs1 += __shfl_xor_sync(~0u, rs1, 2);
        l0 = l0*f0 + rs0; l1 = l1*f1 + rs1;
#pragma unroll
        for (int j = 0; j < 8; j++) {
            o[j][0] *= f0; o[j][1] *= f0; o[j][2] *= f1; o[j][3] *= f1;
        }

        // ---- O += P @ V (V key-major, trans ldmatrix) ----
#pragma unroll
        for (int kg = 0; kg < 4; kg++) {
            const uint32_t a0 = ps[2*kg][0],   a1 = ps[2*kg][1];
            const uint32_t a2 = ps[2*kg+1][0], a3 = ps[2*kg+1][1];
#pragma unroll
            for (int jp = 0; jp < 4; jp++) {
                uint32_t vh[4];
                LDSM4T(vh, vb + (kg*16 + lrow)*QSTR + jp*32 + lsel*16);
                MMAH16816(o[2*jp],   a0,a1,a2,a3, vh[0], vh[1]);
                MMAH16816(o[2*jp+1], a0,a1,a2,a3, vh[2], vh[3]);
            }
        }
        __syncthreads();
    }

    // ---- epilogue ----
    const float inv0 = 1.0f / l0, inv1 = 1.0f / l1;
    const int q0 = qt*128 + wid*16 + gq, q1 = q0 + 8;
#pragma unroll
    for (int j = 0; j < 8; j++) {
        int d0 = j*8 + tq*2;
        if (q0 < NN_) {
            long long off = (long long)(b*NN_ + q0)*CC + h*DD + d0;
            *reinterpret_cast<__half2*>(aoutF + off) = __floats2half2_rn(o[j][0]*inv0, o[j][1]*inv0);
        }
        if (q1 < NN_) {
            long long off = (long long)(b*NN_ + q1)*CC + h*DD + d0;
            *reinterpret_cast<__half2*>(aoutF + off) = __floats2half2_rn(o[j][2]*inv1, o[j][3]*inv1);
        }
    }
}

// ---------------- fused weight fp32 -> fp16 (1 launch) ---------------------
__global__ void conv_all(const float* __restrict__ s0, __half* __restrict__ d0, long long n0,
                         const float* __restrict__ s1, __half* __restrict__ d1, long long n1,
                         const float* __restrict__ s2, __half* __restrict__ d2, long long n2,
                         const float* __restrict__ s3, __half* __restrict__ d3, long long n3)
{
    long long i = (long long)blockIdx.x * blockDim.x + threadIdx.x;
    const float* s; __half* d; long long off;
    if      (i < n0)          { s = s0; d = d0; off = i; }
    else if (i < n0+n1)       { s = s1; d = d1; off = i - n0; }
    else if (i < n0+n1+n2)    { s = s2; d = d2; off = i - n0 - n1; }
    else if (i < n0+n1+n2+n3) { s = s3; d = d3; off = i - n0 - n1 - n2; }
    else return;
    float4 v = reinterpret_cast<const float4*>(s)[off];
    __half2* dp = reinterpret_cast<__half2*>(d) + 2*off;
    dp[0] = __floats2half2_rn(v.x, v.y);
    dp[1] = __floats2half2_rn(v.z, v.w);
}

// ---------------- LayerNorm -> fp16 ----------------------------------------
__global__ void ln_kernel_f(const float* __restrict__ in,
                            const float* __restrict__ w, const float* __restrict__ b,
                            __half* __restrict__ outF)
{
    const long long row = blockIdx.x;
    const int tid = threadIdx.x;
    const float* rp = in + row * CC;
    float v0 = rp[tid], v1 = rp[tid+256], v2 = rp[tid+512];
    float s = v0+v1+v2, ss = v0*v0 + v1*v1 + v2*v2;
    const int wid = tid >> 5, lid = tid & 31;
    for (int o = 16; o; o >>= 1) { s += __shfl_xor_sync(~0u, s, o); ss += __shfl_xor_sync(~0u, ss, o); }
    __shared__ float rs[8], rq[8];
    if (lid == 0) { rs[wid] = s; rq[wid] = ss; }
    __syncthreads();
    float ts = 0.f, tq = 0.f;
#pragma unroll
    for (int i = 0; i < 8; i++) { ts += rs[i]; tq += rq[i]; }
    float mean = ts * (1.0f/CC);
    float rstd = rsqrtf(tq * (1.0f/CC) - mean*mean + EPS_);
#pragma unroll
    for (int k = 0; k < 3; k++) {
        int c = tid + k*256;
        float v = (k==0?v0:(k==1?v1:v2));
        outF[row*CC + c] = __float2half_rn((v - mean)*rstd * w[c] + b[c]);
    }
}

// ---------------------------------------------------------------------------
extern "C" void kernel_launch(void* const* d_in, const int* in_sizes, int n_in,
                              void* d_out, int out_size)
{
    const float* x      = (const float*)d_in[0];
    const float* attn_w = (const float*)d_in[1];
    const float* ln1_w  = (const float*)d_in[2];
    const float* ln1_b  = (const float*)d_in[3];
    const float* qkv_w  = (const float*)d_in[4];
    const float* qkv_b  = (const float*)d_in[5];
    const float* proj_w = (const float*)d_in[6];
    const float* proj_b = (const float*)d_in[7];
    const float* ln2_w  = (const float*)d_in[8];
    const float* ln2_b  = (const float*)d_in[9];
    const float* fc1_w  = (const float*)d_in[10];
    const float* fc1_b  = (const float*)d_in[11];
    const float* fc2_w  = (const float*)d_in[12];
    const float* fc2_b  = (const float*)d_in[13];

    float* out_x     = (float*)d_out;
    float* out_patch = out_x + (long long)ROWS*CC;

    __half *hlnF,*qkvwF,*projwF,*fc1wF,*fc2wF,*qkvF,*aoutF,*h2F,*fc1F;
    float *x1;
    cudaGetSymbolAddress((void**)&hlnF, g_hlnF);
    cudaGetSymbolAddress((void**)&qkvwF, g_qkvwF);
    cudaGetSymbolAddress((void**)&projwF, g_projwF);
    cudaGetSymbolAddress((void**)&fc1wF, g_fc1wF);
    cudaGetSymbolAddress((void**)&fc2wF, g_fc2wF);
    cudaGetSymbolAddress((void**)&qkvF, g_qkvF);
    cudaGetSymbolAddress((void**)&aoutF, g_aoutF);
    cudaGetSymbolAddress((void**)&x1, g_x1);
    cudaGetSymbolAddress((void**)&h2F, g_h2F);
    cudaGetSymbolAddress((void**)&fc1F, g_fc1F);

    const int SMEMHF = 3 * (128*144 + 128*144);     // 110592 (BK=64, 3-stage)
    cudaFuncSetAttribute(gemm_hf<128,0,1>, cudaFuncAttributeMaxDynamicSharedMemorySize, SMEMHF);
    cudaFuncSetAttribute(gemm_hf<128,1,1>, cudaFuncAttributeMaxDynamicSharedMemorySize, SMEMHF);
    cudaFuncSetAttribute(gemm_hf<128,2,0>, cudaFuncAttributeMaxDynamicSharedMemorySize, SMEMHF);
    cudaFuncSetAttribute(flash_attn, cudaFuncAttributeMaxDynamicSharedMemorySize, FLASH_SMEM);

    // 0) all weight conversions in one launch
    const long long n0 = (long long)3*CC*CC/4, n1 = (long long)CC*CC/4;
    const long long n2 = (long long)HID_*CC/4, n3 = (long long)CC*HID_/4;
    conv_all<<<(int)((n0+n1+n2+n3 + 255)/256), 256>>>(
        qkv_w, qkvwF, n0, proj_w, projwF, n1, fc1_w, fc1wF, n2, fc2_w, fc2wF, n3);

    // 1) LN1 -> fp16
    ln_kernel_f<<<ROWS, 256>>>(x, ln1_w, ln1_b, hlnF);

    // 2) qkv = hln @ qkv_w^T + qkv_b -> fp16   (K=768)
    gemm_hf<128,0,1><<<dim3(3*CC/128, (ROWS+127)/128, 1), 256, SMEMHF>>>(
        hlnF, qkvwF, nullptr, qkvF,
        ROWS, 3*CC, CC, CC, CC, 3*CC, qkv_b, nullptr, 0);

    // 3) fused flash attention -> fp16 aout + patch_attn
    flash_attn<<<dim3(5, BB*HH_), 256, FLASH_SMEM>>>(
        qkvF, attn_w, aoutF, out_patch);

    // 4) x1 = x + aout @ proj_w^T + proj_b   (K=768)
    gemm_hf<128,2,0><<<dim3(CC/128, (ROWS+127)/128, 1), 256, SMEMHF>>>(
        aoutF, projwF, x1, nullptr,
        ROWS, CC, CC, CC, CC, CC, proj_b, x, CC);

    // 5) LN2 -> fp16
    ln_kernel_f<<<ROWS, 256>>>(x1, ln2_w, ln2_b, h2F);

    // 6) fc1 = gelu(h2 @ fc1_w^T + fc1_b) -> fp16   (K=768)
    gemm_hf<128,1,1><<<dim3(HID_/128, (ROWS+127)/128, 1), 256, SMEMHF>>>(
        h2F, fc1wF, nullptr, fc1F,
        ROWS, HID_, CC, CC, CC, HID_, fc1_b, nullptr, 0);

    // 7) out = x1 + fc1 @ fc2_w^T + fc2_b   (K=3072)
    gemm_hf<128,2,0><<<dim3(CC/128, (ROWS+127)/128, 1), 256, SMEMHF>>>(
        fc1F, fc2wF, out_x, nullptr,
        ROWS, CC, HID_, HID_, HID_, CC, fc2_b, x1, CC);
}